// round 3
// baseline (speedup 1.0000x reference)
#include <cuda_runtime.h>
#include <cuda_bf16.h>

// Problem constants (fixed by the dataset)
#define NN   100000
#define EE   600000
#define DD   164
#define HH   2
#define DK_  82
#define STEPC 30000
#define NC   20          // EE / STEPC
#define TE   64          // edges per tile in the fused kernel
#define NQ4  41          // DD/4 float4 chunks per row

static __device__ float    g_p[EE * 2];      // scores, then probs
static __device__ unsigned g_maxo[NC * 2];   // ordered-encoded per-chunk-per-head max
static __device__ float    g_sum[NC * 2];    // per-chunk-per-head exp sums

#define INV_SQRT_DK 0.11043152607484654f

// ---------- helpers ----------
__device__ __forceinline__ unsigned fenc(float f) {
    unsigned u = __float_as_uint(f);
    return u ^ ((unsigned)((int)u >> 31) | 0x80000000u);
}
__device__ __forceinline__ float fdec(unsigned u) {
    return __uint_as_float(u ^ ((unsigned)((~(int)u) >> 31) | 0x80000000u));
}
__device__ __forceinline__ unsigned long long pack2(float a, float b) {
    unsigned long long r;
    asm("mov.b64 %0, {%1, %2};" : "=l"(r) : "f"(a), "f"(b));
    return r;
}
__device__ __forceinline__ float2 unpack2(unsigned long long x) {
    float2 r;
    asm("mov.b64 {%0, %1}, %2;" : "=f"(r.x), "=f"(r.y) : "l"(x));
    return r;
}
#define FMA2(acc, a, b) \
    asm("fma.rn.f32x2 %0, %1, %2, %0;" : "+l"(acc) : "l"(a), "l"(b))

__device__ __forceinline__ float fast_tanh(float x) {
    // tanh(x) = 1 - 2/(exp(2x)+1); exact saturation at +/-inf of __expf
    float e = __expf(2.0f * x);
    return 1.0f - 2.0f / (e + 1.0f);
}

// ---------- kernel 0: reset scratch ----------
__global__ void init_scratch_kernel() {
    int i = threadIdx.x;
    if (i < NC * 2) { g_maxo[i] = 0u; g_sum[i] = 0.0f; }
}

// ---------- kernel 1: scores + per-chunk max ----------
__global__ void score_kernel(const float* __restrict__ q, const float* __restrict__ k,
                             const int* __restrict__ ei, const float* __restrict__ rb) {
    __shared__ unsigned smax[NC * 2];
    for (int i = threadIdx.x; i < NC * 2; i += blockDim.x) smax[i] = 0u;
    __syncthreads();

    const float rb0 = rb[0], rb1 = rb[1];
    const int lane  = threadIdx.x & 31;
    const int gwarp = (blockIdx.x * blockDim.x + threadIdx.x) >> 5;
    const int nw    = (gridDim.x * blockDim.x) >> 5;

    for (int e = gwarp; e < EE; e += nw) {
        const int sN = ei[e];
        const int dN = ei[EE + e];
        const float* qr = q + (long long)dN * DD;
        const float* kr = k + (long long)sN * DD;
        float s0 = 0.0f, s1 = 0.0f;
#pragma unroll
        for (int j = 0; j < 6; j++) {
            int dd = lane + 32 * j;
            if (dd < DD) {
                float p = qr[dd] * kr[dd];
                if (dd < DK_) s0 += p; else s1 += p;
            }
        }
#pragma unroll
        for (int o = 16; o; o >>= 1) {
            s0 += __shfl_xor_sync(0xffffffffu, s0, o);
            s1 += __shfl_xor_sync(0xffffffffu, s1, o);
        }
        if (lane == 0) {
            float sc0 = fmaf(s0, INV_SQRT_DK, rb0);
            float sc1 = fmaf(s1, INV_SQRT_DK, rb1);
            g_p[2 * e]     = sc0;
            g_p[2 * e + 1] = sc1;
            int c = e / STEPC;
            atomicMax(&smax[2 * c],     fenc(sc0));
            atomicMax(&smax[2 * c + 1], fenc(sc1));
        }
    }
    __syncthreads();
    for (int i = threadIdx.x; i < NC * 2; i += blockDim.x)
        if (smax[i]) atomicMax(&g_maxo[i], smax[i]);
}

// ---------- kernel 2: exp + per-chunk sums ----------
__global__ void expsum_kernel() {
    __shared__ float ssum[NC * 2];
    for (int i = threadIdx.x; i < NC * 2; i += blockDim.x) ssum[i] = 0.0f;
    __syncthreads();

    const int gtid = blockIdx.x * blockDim.x + threadIdx.x;
    const int nt   = gridDim.x * blockDim.x;
    for (int e = gtid; e < EE; e += nt) {
        int c = e / STEPC;
        float m0 = fdec(g_maxo[2 * c]);
        float m1 = fdec(g_maxo[2 * c + 1]);
        float p0 = __expf(g_p[2 * e]     - m0);
        float p1 = __expf(g_p[2 * e + 1] - m1);
        g_p[2 * e]     = p0;
        g_p[2 * e + 1] = p1;
        atomicAdd(&ssum[2 * c],     p0);
        atomicAdd(&ssum[2 * c + 1], p1);
    }
    __syncthreads();
    for (int i = threadIdx.x; i < NC * 2; i += blockDim.x)
        if (ssum[i] != 0.0f) atomicAdd(&g_sum[i], ssum[i]);
}

// ---------- kernel 3: fused FiLM MLP + att * modulated-v + scatter ----------
struct Smem {
    float2 W2p[DK_ * DD];       // [k][d]: (W2[d,k], W2[d+164,k])   107584 B
    float  W1t[24 * DK_];       // [f][r]                             7872 B
    float  b1s[DK_];
    float2 b2p[DD];             // (b2[d], b2[d+164])
    float  feat[TE * 24];
    float  hmid[TE * DK_];
    float  pad0[2];             // 16B-align Sm for float4 access
    float  Sm[TE * DD];
};

__global__ void __launch_bounds__(256, 1)
film_attn_kernel(const int* __restrict__ ei, const float* __restrict__ edge_attr,
                 const float* __restrict__ edge_time, const float* __restrict__ Wt,
                 const float* __restrict__ bt, const float* __restrict__ W1,
                 const float* __restrict__ b1, const float* __restrict__ W2,
                 const float* __restrict__ b2, const float* __restrict__ v,
                 float* __restrict__ out) {
    extern __shared__ char sraw[];
    Smem& S = *reinterpret_cast<Smem*>(sraw);
    const int tid = threadIdx.x;

    // stage weights (coalesced gmem reads, one-time)
    for (int idx = tid; idx < 328 * DK_; idx += 256) {
        int g = idx / DK_, kk = idx % DK_;
        float w = W2[idx];
        int d = (g < DD) ? g : g - DD;
        float* base = reinterpret_cast<float*>(&S.W2p[kk * DD + d]);
        base[(g < DD) ? 0 : 1] = w;
    }
    for (int idx = tid; idx < DK_ * 24; idx += 256) {
        int r = idx / 24, f = idx % 24;
        S.W1t[f * DK_ + r] = W1[idx];
    }
    for (int idx = tid; idx < DK_; idx += 256) S.b1s[idx] = b1[idx];
    for (int idx = tid; idx < DD; idx += 256)
        S.b2p[idx] = make_float2(b2[idx], b2[idx + DD]);
    __syncthreads();

    const int tx = tid & 31;
    const int ty = tid >> 5;
    const bool d5ok  = (tx < 4);
    const int  d5idx = d5ok ? (160 + tx) : 0;

    for (int tile = blockIdx.x; tile < EE / TE; tile += gridDim.x) {
        const int e0 = tile * TE;

        // phase 1: build feat = [edge_attr(16) | time_pe(8)]
        for (int idx = tid; idx < TE * 24; idx += 256) {
            int el = idx / 24, f = idx % 24;
            int e = e0 + el;
            float val;
            if (f < 16) val = edge_attr[(long long)e * 16 + f];
            else        val = fmaf(edge_time[e], Wt[f - 16], bt[f - 16]);
            S.feat[el * 24 + f] = val;
        }
        __syncthreads();

        // phase 2: hmid = relu(W1 @ feat + b1), [TE x 82]
        {
            float acc[3][8];
#pragma unroll
            for (int m = 0; m < 3; m++) {
                int r = tx + 32 * m;
                float bb = (r < DK_) ? S.b1s[r] : 0.0f;
#pragma unroll
                for (int i = 0; i < 8; i++) acc[m][i] = bb;
            }
            const int r2 = (tx + 64 < DK_) ? (tx + 64) : 0;
#pragma unroll 4
            for (int f = 0; f < 24; f++) {
                float w0 = S.W1t[f * DK_ + tx];
                float w1 = S.W1t[f * DK_ + tx + 32];
                float w2v = S.W1t[f * DK_ + r2];
#pragma unroll
                for (int i = 0; i < 8; i++) {
                    float h = S.feat[(ty + 8 * i) * 24 + f];
                    acc[0][i] = fmaf(w0,  h, acc[0][i]);
                    acc[1][i] = fmaf(w1,  h, acc[1][i]);
                    acc[2][i] = fmaf(w2v, h, acc[2][i]);
                }
            }
#pragma unroll
            for (int m = 0; m < 3; m++) {
                int r = tx + 32 * m;
                if (r < DK_) {
#pragma unroll
                    for (int i = 0; i < 8; i++)
                        S.hmid[(ty + 8 * i) * DK_ + r] = fmaxf(acc[m][i], 0.0f);
                }
            }
        }
        __syncthreads();

        // phase 3: gb = W2 @ hmid + b2 as (gamma,beta)-paired f32x2 GEMM
        {
            unsigned long long acc2[6][8];
#pragma unroll
            for (int m = 0; m < 6; m++) {
                int d = (m < 5) ? (tx + 32 * m) : d5idx;
                float2 bb = S.b2p[d];
                unsigned long long bp = pack2(bb.x, bb.y);
#pragma unroll
                for (int i = 0; i < 8; i++) acc2[m][i] = bp;
            }
#pragma unroll 2
            for (int kk = 0; kk < DK_; kk++) {
                unsigned long long hp[8];
#pragma unroll
                for (int i = 0; i < 8; i++) {
                    float h = S.hmid[(ty + 8 * i) * DK_ + kk];
                    hp[i] = pack2(h, h);
                }
#pragma unroll
                for (int m = 0; m < 6; m++) {
                    int d = (m < 5) ? (tx + 32 * m) : d5idx;
                    unsigned long long wp =
                        *reinterpret_cast<const unsigned long long*>(&S.W2p[kk * DD + d]);
#pragma unroll
                    for (int i = 0; i < 8; i++)
                        FMA2(acc2[m][i], wp, hp[i]);
                }
            }

            // epilogue: tanh, v-modulation, attention weight -> Sm
#pragma unroll
            for (int i = 0; i < 8; i++) {
                const int el = ty + 8 * i;
                const int e  = e0 + el;
                const int c  = e / STEPC;
                const float p0 = g_p[2 * e];
                const float p1 = g_p[2 * e + 1];
                const float a0 = p0 / g_sum[2 * c];
                const float a1 = p1 / g_sum[2 * c + 1];
                const int sN = ei[e];
                const float* vrow = v + (long long)sN * DD;
#pragma unroll
                for (int m = 0; m < 6; m++) {
                    int d = tx + 32 * m;
                    if (d < DD) {
                        float2 gb = unpack2(acc2[m][i]);
                        float ga = fast_tanh(gb.x);
                        float be = fast_tanh(gb.y);
                        float att = (d < DK_) ? a0 : a1;
                        float vv = vrow[d];
                        S.Sm[el * DD + d] = att * fmaf(vv, 1.0f + ga, be);
                    }
                }
            }
        }
        __syncthreads();

        // phase 4: vectorized scatter-add to out[dst]
        for (int idx = tid; idx < TE * NQ4; idx += 256) {
            int el = idx / NQ4, c4 = idx % NQ4;
            int dN = ei[EE + e0 + el];
            float4 val = *reinterpret_cast<const float4*>(&S.Sm[el * DD + c4 * 4]);
            float* p = out + (long long)dN * DD + c4 * 4;
            asm volatile("red.global.add.v4.f32 [%0], {%1, %2, %3, %4};"
                         :: "l"(p), "f"(val.x), "f"(val.y), "f"(val.z), "f"(val.w)
                         : "memory");
        }
        __syncthreads();
    }
}

extern "C" void kernel_launch(void* const* d_in, const int* in_sizes, int n_in,
                              void* d_out, int out_size) {
    const float* q         = (const float*)d_in[0];
    const float* k         = (const float*)d_in[1];
    const float* v         = (const float*)d_in[2];
    const int*   ei        = (const int*)  d_in[3];
    const float* edge_attr = (const float*)d_in[4];
    const float* edge_time = (const float*)d_in[5];
    const float* Wt        = (const float*)d_in[6];
    const float* bt        = (const float*)d_in[7];
    const float* W1        = (const float*)d_in[8];
    const float* b1        = (const float*)d_in[9];
    const float* W2        = (const float*)d_in[10];
    const float* b2        = (const float*)d_in[11];
    const float* rb        = (const float*)d_in[12];
    float* out = (float*)d_out;

    cudaMemsetAsync(d_out, 0, (size_t)out_size * sizeof(float), 0);
    init_scratch_kernel<<<1, 64>>>();
    score_kernel<<<1184, 256>>>(q, k, ei, rb);
    expsum_kernel<<<1184, 256>>>();

    const int smem_bytes = (int)sizeof(Smem);
    cudaFuncSetAttribute(film_attn_kernel,
                         cudaFuncAttributeMaxDynamicSharedMemorySize, smem_bytes);
    film_attn_kernel<<<152, 256, smem_bytes>>>(ei, edge_attr, edge_time, Wt, bt,
                                               W1, b1, W2, b2, v, out);
}

// round 8
// speedup vs baseline: 1.3183x; 1.3183x over previous
#include <cuda_runtime.h>
#include <cuda_bf16.h>

// Problem constants (fixed by the dataset)
#define NN   100000
#define EE   600000
#define DD   164
#define HH   2
#define DK_  82
#define STEPC 30000
#define NC   20          // EE / STEPC
#define TE   64          // edges per tile in the fused kernel
#define NQ4  41          // DD/4 float4 chunks per row

static __device__ float    g_p[EE * 2];      // scores, then probs
static __device__ unsigned g_maxo[NC * 2];   // ordered-encoded per-chunk-per-head max
static __device__ float    g_sum[NC * 2];    // per-chunk-per-head exp sums

#define INV_SQRT_DK 0.11043152607484654f

// ---------- helpers ----------
__device__ __forceinline__ unsigned fenc(float f) {
    unsigned u = __float_as_uint(f);
    return u ^ ((unsigned)((int)u >> 31) | 0x80000000u);
}
__device__ __forceinline__ float fdec(unsigned u) {
    return __uint_as_float(u ^ ((unsigned)((~(int)u) >> 31) | 0x80000000u));
}
__device__ __forceinline__ unsigned long long pack2(float a, float b) {
    unsigned long long r;
    asm("mov.b64 %0, {%1, %2};" : "=l"(r) : "f"(a), "f"(b));
    return r;
}
__device__ __forceinline__ unsigned long long dup2(float a) {
    unsigned long long r;
    asm("mov.b64 %0, {%1, %1};" : "=l"(r) : "f"(a));
    return r;
}
__device__ __forceinline__ float2 unpack2(unsigned long long x) {
    float2 r;
    asm("mov.b64 {%0, %1}, %2;" : "=f"(r.x), "=f"(r.y) : "l"(x));
    return r;
}
#define FMA2(acc, a, b) \
    asm("fma.rn.f32x2 %0, %1, %2, %0;" : "+l"(acc) : "l"(a), "l"(b))

__device__ __forceinline__ float fast_tanh(float x) {
    float e = __expf(2.0f * x);
    return 1.0f - 2.0f / (e + 1.0f);
}

// ---------- kernel 0: reset scratch ----------
__global__ void init_scratch_kernel() {
    int i = threadIdx.x;
    if (i < NC * 2) { g_maxo[i] = 0u; g_sum[i] = 0.0f; }
}

// ---------- kernel 1: scores + per-chunk max (vectorized rows) ----------
// Row has 41 float4 chunks: lanes 0..31 take chunks 0..31 (d 0..127);
// lanes 0..8 additionally take chunks 32..40 (d 128..163, all head 1).
__global__ void score_kernel(const float* __restrict__ q, const float* __restrict__ k,
                             const int* __restrict__ ei, const float* __restrict__ rb) {
    __shared__ unsigned smax[NC * 2];
    for (int i = threadIdx.x; i < NC * 2; i += blockDim.x) smax[i] = 0u;
    __syncthreads();

    const float rb0 = rb[0], rb1 = rb[1];
    const int lane  = threadIdx.x & 31;
    const int gwarp = (blockIdx.x * blockDim.x + threadIdx.x) >> 5;
    const int nw    = (gridDim.x * blockDim.x) >> 5;

    for (int e = gwarp; e < EE; e += nw) {
        const int sN = ei[e];
        const int dN = ei[EE + e];
        const float* qr = q + (long long)dN * DD;
        const float* kr = k + (long long)sN * DD;
        float s0 = 0.0f, s1 = 0.0f;
        {
            const float4 q4 = *reinterpret_cast<const float4*>(qr + lane * 4);
            const float4 k4 = *reinterpret_cast<const float4*>(kr + lane * 4);
            float px = q4.x * k4.x, py = q4.y * k4.y, pz = q4.z * k4.z, pw = q4.w * k4.w;
            float all = (px + py) + (pz + pw);
            if (lane < 20)      { s0 = all; }
            else if (lane == 20){ s0 = px + py; s1 = pz + pw; }   // d 80,81 | 82,83
            else                { s1 = all; }
        }
        if (lane < 9) {   // chunks 32..40 -> d 128..163, entirely head 1
            const float4 q4 = *reinterpret_cast<const float4*>(qr + 128 + lane * 4);
            const float4 k4 = *reinterpret_cast<const float4*>(kr + 128 + lane * 4);
            s1 += (q4.x * k4.x + q4.y * k4.y) + (q4.z * k4.z + q4.w * k4.w);
        }
#pragma unroll
        for (int o = 16; o; o >>= 1) {
            s0 += __shfl_xor_sync(0xffffffffu, s0, o);
            s1 += __shfl_xor_sync(0xffffffffu, s1, o);
        }
        if (lane == 0) {
            float sc0 = fmaf(s0, INV_SQRT_DK, rb0);
            float sc1 = fmaf(s1, INV_SQRT_DK, rb1);
            g_p[2 * e]     = sc0;
            g_p[2 * e + 1] = sc1;
            int c = e / STEPC;
            atomicMax(&smax[2 * c],     fenc(sc0));
            atomicMax(&smax[2 * c + 1], fenc(sc1));
        }
    }
    __syncthreads();
    for (int i = threadIdx.x; i < NC * 2; i += blockDim.x)
        if (smax[i]) atomicMax(&g_maxo[i], smax[i]);
}

// ---------- kernel 2: exp + per-chunk sums ----------
__global__ void expsum_kernel() {
    __shared__ float ssum[NC * 2];
    for (int i = threadIdx.x; i < NC * 2; i += blockDim.x) ssum[i] = 0.0f;
    __syncthreads();

    const int gtid = blockIdx.x * blockDim.x + threadIdx.x;
    const int nt   = gridDim.x * blockDim.x;
    for (int e = gtid; e < EE; e += nt) {
        int c = e / STEPC;
        float m0 = fdec(g_maxo[2 * c]);
        float m1 = fdec(g_maxo[2 * c + 1]);
        float p0 = __expf(g_p[2 * e]     - m0);
        float p1 = __expf(g_p[2 * e + 1] - m1);
        g_p[2 * e]     = p0;
        g_p[2 * e + 1] = p1;
        atomicAdd(&ssum[2 * c],     p0);
        atomicAdd(&ssum[2 * c + 1], p1);
    }
    __syncthreads();
    for (int i = threadIdx.x; i < NC * 2; i += blockDim.x)
        if (ssum[i] != 0.0f) atomicAdd(&g_sum[i], ssum[i]);
}

// ---------- kernel 3: fused FiLM MLP + att * modulated-v + scatter ----------
// 512 threads / 16 warps. Phase-3 split: warp = (edge-group ew = warp>>1, d-half mh = warp&1).
struct Smem {
    float2 W2p[DK_ * DD];       // [k][d]: (W2[d,k], W2[d+164,k])   107584 B
    float  W1t[24 * DK_];       // [f][r]                             7872 B
    float  b1s[DK_];
    float2 b2p[DD];             // (b2[d], b2[d+164])
    float  feat[TE * 24];
    float  hmid[TE * DK_];      // 82 even -> float2 loads on even k are 8B-aligned
    float  pad0[2];             // 16B-align Sm for float4 access
    float  Sm[TE * DD];
};

#define NT 512

__global__ void __launch_bounds__(NT, 1)
film_attn_kernel(const int* __restrict__ ei, const float* __restrict__ edge_attr,
                 const float* __restrict__ edge_time, const float* __restrict__ Wt,
                 const float* __restrict__ bt, const float* __restrict__ W1,
                 const float* __restrict__ b1, const float* __restrict__ W2,
                 const float* __restrict__ b2, const float* __restrict__ v,
                 float* __restrict__ out) {
    extern __shared__ char sraw[];
    Smem& S = *reinterpret_cast<Smem*>(sraw);
    const int tid = threadIdx.x;

    // stage weights (coalesced gmem reads, one-time)
    for (int idx = tid; idx < 328 * DK_; idx += NT) {
        int g = idx / DK_, kk = idx % DK_;
        float w = W2[idx];
        int d = (g < DD) ? g : g - DD;
        float* base = reinterpret_cast<float*>(&S.W2p[kk * DD + d]);
        base[(g < DD) ? 0 : 1] = w;
    }
    for (int idx = tid; idx < DK_ * 24; idx += NT) {
        int r = idx / 24, f = idx % 24;
        S.W1t[f * DK_ + r] = W1[idx];
    }
    for (int idx = tid; idx < DK_; idx += NT) S.b1s[idx] = b1[idx];
    for (int idx = tid; idx < DD; idx += NT)
        S.b2p[idx] = make_float2(b2[idx], b2[idx + DD]);
    __syncthreads();

    const int tx   = tid & 31;
    const int warp = tid >> 5;        // 0..15
    const int mh   = warp & 1;        // d-half: m-slots {0,1,2} or {3,4,5}
    const int ew   = warp >> 1;       // 0..7, edge group of 8
    const int elb  = ew * 8;

    for (int tile = blockIdx.x; tile < EE / TE; tile += gridDim.x) {
        const int e0 = tile * TE;

        // phase 1: build feat = [edge_attr(16) | time_pe(8)]
        for (int idx = tid; idx < TE * 24; idx += NT) {
            int el = idx / 24, f = idx % 24;
            int e = e0 + el;
            float val;
            if (f < 16) val = edge_attr[(long long)e * 16 + f];
            else        val = fmaf(edge_time[e], Wt[f - 16], bt[f - 16]);
            S.feat[el * 24 + f] = val;
        }
        __syncthreads();

        // phase 2: hmid = relu(W1 @ feat + b1), [TE x 82]; each warp: 4 edges
        {
            float acc[3][4];
#pragma unroll
            for (int m = 0; m < 3; m++) {
                int r = tx + 32 * m;
                float bb = (r < DK_) ? S.b1s[r] : 0.0f;
#pragma unroll
                for (int i = 0; i < 4; i++) acc[m][i] = bb;
            }
            const int r2 = (tx + 64 < DK_) ? (tx + 64) : 0;
#pragma unroll 4
            for (int f = 0; f < 24; f++) {
                float w0  = S.W1t[f * DK_ + tx];
                float w1  = S.W1t[f * DK_ + tx + 32];
                float w2v = S.W1t[f * DK_ + r2];
#pragma unroll
                for (int i = 0; i < 4; i++) {
                    float h = S.feat[(warp + 16 * i) * 24 + f];
                    acc[0][i] = fmaf(w0,  h, acc[0][i]);
                    acc[1][i] = fmaf(w1,  h, acc[1][i]);
                    acc[2][i] = fmaf(w2v, h, acc[2][i]);
                }
            }
#pragma unroll
            for (int m = 0; m < 3; m++) {
                int r = tx + 32 * m;
                if (r < DK_) {
#pragma unroll
                    for (int i = 0; i < 4; i++)
                        S.hmid[(warp + 16 * i) * DK_ + r] = fmaxf(acc[m][i], 0.0f);
                }
            }
        }
        __syncthreads();

        // phase 3: gb = W2 @ hmid + b2 as (gamma,beta)-paired f32x2 GEMM
        // warp covers m-slots [3*mh, 3*mh+3) x edges [elb, elb+8)
        {
            unsigned long long acc2[3][8];
#pragma unroll
            for (int mm = 0; mm < 3; mm++) {
                int mg = 3 * mh + mm;
                int d  = tx + 32 * mg;
                int dd = (d < DD) ? d : 0;
                float2 bb = S.b2p[dd];
                unsigned long long bp = pack2(bb.x, bb.y);
#pragma unroll
                for (int i = 0; i < 8; i++) acc2[mm][i] = bp;
            }
            const int dA = tx + 32 * (3 * mh + 0);
            const int dB = tx + 32 * (3 * mh + 1);
            const int dCr = tx + 32 * (3 * mh + 2);
            const int dC = (dCr < DD) ? dCr : 0;          // mh=1,tx>=4 dummy

            for (int kk = 0; kk < DK_; kk += 2) {
                unsigned long long hp0[8], hp1[8];
#pragma unroll
                for (int i = 0; i < 8; i++) {
                    float2 h2 = *reinterpret_cast<const float2*>(
                        &S.hmid[(elb + i) * DK_ + kk]);      // broadcast LDS.64
                    hp0[i] = dup2(h2.x);
                    hp1[i] = dup2(h2.y);
                }
                const unsigned long long* w0row =
                    reinterpret_cast<const unsigned long long*>(&S.W2p[kk * DD]);
                const unsigned long long* w1row =
                    reinterpret_cast<const unsigned long long*>(&S.W2p[(kk + 1) * DD]);
                unsigned long long wA0 = w0row[dA], wA1 = w1row[dA];
                unsigned long long wB0 = w0row[dB], wB1 = w1row[dB];
                unsigned long long wC0 = w0row[dC], wC1 = w1row[dC];
#pragma unroll
                for (int i = 0; i < 8; i++) {
                    FMA2(acc2[0][i], wA0, hp0[i]);
                    FMA2(acc2[1][i], wB0, hp0[i]);
                    FMA2(acc2[2][i], wC0, hp0[i]);
                    FMA2(acc2[0][i], wA1, hp1[i]);
                    FMA2(acc2[1][i], wB1, hp1[i]);
                    FMA2(acc2[2][i], wC1, hp1[i]);
                }
            }

            // epilogue: tanh, v-modulation, attention weight -> Sm
#pragma unroll
            for (int i = 0; i < 8; i++) {
                const int el = elb + i;
                const int e  = e0 + el;
                const int c  = e / STEPC;
                const float a0 = g_p[2 * e]     / g_sum[2 * c];
                const float a1 = g_p[2 * e + 1] / g_sum[2 * c + 1];
                const int sN = ei[e];
                const float* vrow = v + (long long)sN * DD;
#pragma unroll
                for (int mm = 0; mm < 3; mm++) {
                    int d = tx + 32 * (3 * mh + mm);
                    if (d < DD) {
                        float2 gb = unpack2(acc2[mm][i]);
                        float ga = fast_tanh(gb.x);
                        float be = fast_tanh(gb.y);
                        float att = (d < DK_) ? a0 : a1;
                        float vv = vrow[d];
                        S.Sm[el * DD + d] = att * fmaf(vv, 1.0f + ga, be);
                    }
                }
            }
        }
        __syncthreads();

        // phase 4: vectorized scatter-add to out[dst]
        for (int idx = tid; idx < TE * NQ4; idx += NT) {
            int el = idx / NQ4, c4 = idx % NQ4;
            int dN = ei[EE + e0 + el];
            float4 val = *reinterpret_cast<const float4*>(&S.Sm[el * DD + c4 * 4]);
            float* p = out + (long long)dN * DD + c4 * 4;
            asm volatile("red.global.add.v4.f32 [%0], {%1, %2, %3, %4};"
                         :: "l"(p), "f"(val.x), "f"(val.y), "f"(val.z), "f"(val.w)
                         : "memory");
        }
        __syncthreads();
    }
}

extern "C" void kernel_launch(void* const* d_in, const int* in_sizes, int n_in,
                              void* d_out, int out_size) {
    const float* q         = (const float*)d_in[0];
    const float* k         = (const float*)d_in[1];
    const float* v         = (const float*)d_in[2];
    const int*   ei        = (const int*)  d_in[3];
    const float* edge_attr = (const float*)d_in[4];
    const float* edge_time = (const float*)d_in[5];
    const float* Wt        = (const float*)d_in[6];
    const float* bt        = (const float*)d_in[7];
    const float* W1        = (const float*)d_in[8];
    const float* b1        = (const float*)d_in[9];
    const float* W2        = (const float*)d_in[10];
    const float* b2        = (const float*)d_in[11];
    const float* rb        = (const float*)d_in[12];
    float* out = (float*)d_out;

    cudaMemsetAsync(d_out, 0, (size_t)out_size * sizeof(float), 0);
    init_scratch_kernel<<<1, 64>>>();
    score_kernel<<<1184, 256>>>(q, k, ei, rb);
    expsum_kernel<<<1184, 256>>>();

    const int smem_bytes = (int)sizeof(Smem);
    cudaFuncSetAttribute(film_attn_kernel,
                         cudaFuncAttributeMaxDynamicSharedMemorySize, smem_bytes);
    film_attn_kernel<<<152, NT, smem_bytes>>>(ei, edge_attr, edge_time, Wt, bt,
                                              W1, b1, W2, b2, v, out);
}

// round 9
// speedup vs baseline: 1.7924x; 1.3596x over previous
#include <cuda_runtime.h>
#include <cuda_bf16.h>

// Problem constants (fixed by the dataset)
#define NN   100000
#define EE   600000
#define DD   164
#define HH   2
#define DK_  82
#define STEPC 30000
#define NC   20          // EE / STEPC
#define TE   64          // edges per tile in the fused kernel
#define NQ4  41          // DD/4 float4 chunks per row

static __device__ float    g_p[EE * 2];      // scores, then probs
static __device__ unsigned g_maxo[NC * 2];   // ordered-encoded per-chunk-per-head max
static __device__ float    g_sum[NC * 2];    // per-chunk-per-head exp sums

#define INV_SQRT_DK 0.11043152607484654f

// ---------- helpers ----------
__device__ __forceinline__ unsigned fenc(float f) {
    unsigned u = __float_as_uint(f);
    return u ^ ((unsigned)((int)u >> 31) | 0x80000000u);
}
__device__ __forceinline__ float fdec(unsigned u) {
    return __uint_as_float(u ^ ((unsigned)((~(int)u) >> 31) | 0x80000000u));
}
__device__ __forceinline__ unsigned long long pack2(float a, float b) {
    unsigned long long r;
    asm("mov.b64 %0, {%1, %2};" : "=l"(r) : "f"(a), "f"(b));
    return r;
}
__device__ __forceinline__ unsigned long long dup2(float a) {
    unsigned long long r;
    asm("mov.b64 %0, {%1, %1};" : "=l"(r) : "f"(a));
    return r;
}
__device__ __forceinline__ float2 unpack2(unsigned long long x) {
    float2 r;
    asm("mov.b64 {%0, %1}, %2;" : "=f"(r.x), "=f"(r.y) : "l"(x));
    return r;
}
#define FMA2(acc, a, b) \
    asm("fma.rn.f32x2 %0, %1, %2, %0;" : "+l"(acc) : "l"(a), "l"(b))

__device__ __forceinline__ float fast_tanh(float x) {
    float e = __expf(2.0f * x);
    return 1.0f - 2.0f / (e + 1.0f);
}

__device__ __forceinline__ void cp_async16(unsigned smem_dst, const void* gsrc) {
    asm volatile("cp.async.ca.shared.global [%0], [%1], 16;"
                 :: "r"(smem_dst), "l"(gsrc) : "memory");
}

// ---------- kernel 0: reset scratch ----------
__global__ void init_scratch_kernel() {
    int i = threadIdx.x;
    if (i < NC * 2) { g_maxo[i] = 0u; g_sum[i] = 0.0f; }
}

// ---------- kernel 1: scores + per-chunk max (vectorized rows) ----------
// Row has 41 float4 chunks: lanes 0..31 take chunks 0..31 (d 0..127);
// lanes 0..8 additionally take chunks 32..40 (d 128..163, all head 1).
__global__ void score_kernel(const float* __restrict__ q, const float* __restrict__ k,
                             const int* __restrict__ ei, const float* __restrict__ rb) {
    __shared__ unsigned smax[NC * 2];
    for (int i = threadIdx.x; i < NC * 2; i += blockDim.x) smax[i] = 0u;
    __syncthreads();

    const float rb0 = rb[0], rb1 = rb[1];
    const int lane  = threadIdx.x & 31;
    const int gwarp = (blockIdx.x * blockDim.x + threadIdx.x) >> 5;
    const int nw    = (gridDim.x * blockDim.x) >> 5;

    for (int e = gwarp; e < EE; e += nw) {
        const int sN = ei[e];
        const int dN = ei[EE + e];
        const float* qr = q + (long long)dN * DD;
        const float* kr = k + (long long)sN * DD;
        float s0 = 0.0f, s1 = 0.0f;
        {
            const float4 q4 = *reinterpret_cast<const float4*>(qr + lane * 4);
            const float4 k4 = *reinterpret_cast<const float4*>(kr + lane * 4);
            float px = q4.x * k4.x, py = q4.y * k4.y, pz = q4.z * k4.z, pw = q4.w * k4.w;
            float all = (px + py) + (pz + pw);
            if (lane < 20)      { s0 = all; }
            else if (lane == 20){ s0 = px + py; s1 = pz + pw; }   // d 80,81 | 82,83
            else                { s1 = all; }
        }
        if (lane < 9) {   // chunks 32..40 -> d 128..163, entirely head 1
            const float4 q4 = *reinterpret_cast<const float4*>(qr + 128 + lane * 4);
            const float4 k4 = *reinterpret_cast<const float4*>(kr + 128 + lane * 4);
            s1 += (q4.x * k4.x + q4.y * k4.y) + (q4.z * k4.z + q4.w * k4.w);
        }
#pragma unroll
        for (int o = 16; o; o >>= 1) {
            s0 += __shfl_xor_sync(0xffffffffu, s0, o);
            s1 += __shfl_xor_sync(0xffffffffu, s1, o);
        }
        if (lane == 0) {
            float sc0 = fmaf(s0, INV_SQRT_DK, rb0);
            float sc1 = fmaf(s1, INV_SQRT_DK, rb1);
            g_p[2 * e]     = sc0;
            g_p[2 * e + 1] = sc1;
            int c = e / STEPC;
            atomicMax(&smax[2 * c],     fenc(sc0));
            atomicMax(&smax[2 * c + 1], fenc(sc1));
        }
    }
    __syncthreads();
    for (int i = threadIdx.x; i < NC * 2; i += blockDim.x)
        if (smax[i]) atomicMax(&g_maxo[i], smax[i]);
}

// ---------- kernel 2: exp + per-chunk sums ----------
__global__ void expsum_kernel() {
    __shared__ float ssum[NC * 2];
    for (int i = threadIdx.x; i < NC * 2; i += blockDim.x) ssum[i] = 0.0f;
    __syncthreads();

    const int gtid = blockIdx.x * blockDim.x + threadIdx.x;
    const int nt   = gridDim.x * blockDim.x;
    for (int e = gtid; e < EE; e += nt) {
        int c = e / STEPC;
        float m0 = fdec(g_maxo[2 * c]);
        float m1 = fdec(g_maxo[2 * c + 1]);
        float p0 = __expf(g_p[2 * e]     - m0);
        float p1 = __expf(g_p[2 * e + 1] - m1);
        g_p[2 * e]     = p0;
        g_p[2 * e + 1] = p1;
        atomicAdd(&ssum[2 * c],     p0);
        atomicAdd(&ssum[2 * c + 1], p1);
    }
    __syncthreads();
    for (int i = threadIdx.x; i < NC * 2; i += blockDim.x)
        if (ssum[i] != 0.0f) atomicAdd(&g_sum[i], ssum[i]);
}

// ---------- kernel 3: fused FiLM MLP + att * modulated-v + scatter ----------
// 512 threads / 16 warps. Phase-3 split: warp = (edge-group ew = warp>>1, d-half mh = warp&1).
// v rows are prefetched into Sm via cp.async during the k-loop; the epilogue
// reads v from Sm and overwrites the same slot in place.
struct Smem {
    float2 W2p[DK_ * DD];       // [k][d]: (W2[d,k], W2[d+164,k])   107584 B
    float  W1t[24 * DK_];       // [f][r]                             7872 B
    float  b1s[DK_];            // 328 B
    float2 b2p[DD];             // (b2[d], b2[d+164])                 1312 B
    float  feat[TE * 24];       // 6144 B
    float  hmid[TE * DK_];      // 20992 B; Sm ends 16B-aligned below
    float  pad0[2];
    float  Sm[TE * DD];         // 41984 B (v prefetch, then output staging)
    int    s_src[TE];
    int    s_dst[TE];
    float  s_att[TE * 2];       // (a0, a1) per edge
};

#define NT 512

__global__ void __launch_bounds__(NT, 1)
film_attn_kernel(const int* __restrict__ ei, const float* __restrict__ edge_attr,
                 const float* __restrict__ edge_time, const float* __restrict__ Wt,
                 const float* __restrict__ bt, const float* __restrict__ W1,
                 const float* __restrict__ b1, const float* __restrict__ W2,
                 const float* __restrict__ b2, const float* __restrict__ v,
                 float* __restrict__ out) {
    extern __shared__ char sraw[];
    Smem& S = *reinterpret_cast<Smem*>(sraw);
    const int tid = threadIdx.x;

    // stage weights (coalesced gmem reads, one-time)
    for (int idx = tid; idx < 328 * DK_; idx += NT) {
        int g = idx / DK_, kk = idx % DK_;
        float w = W2[idx];
        int d = (g < DD) ? g : g - DD;
        float* base = reinterpret_cast<float*>(&S.W2p[kk * DD + d]);
        base[(g < DD) ? 0 : 1] = w;
    }
    for (int idx = tid; idx < DK_ * 24; idx += NT) {
        int r = idx / 24, f = idx % 24;
        S.W1t[f * DK_ + r] = W1[idx];
    }
    for (int idx = tid; idx < DK_; idx += NT) S.b1s[idx] = b1[idx];
    for (int idx = tid; idx < DD; idx += NT)
        S.b2p[idx] = make_float2(b2[idx], b2[idx + DD]);
    __syncthreads();

    const int tx   = tid & 31;
    const int warp = tid >> 5;        // 0..15
    const int mh   = warp & 1;        // d-half: m-slots {0,1,2} or {3,4,5}
    const int ew   = warp >> 1;       // 0..7, edge group of 8
    const int elb  = ew * 8;
    const unsigned smSm = (unsigned)__cvta_generic_to_shared(&S.Sm[0]);

    for (int tile = blockIdx.x; tile < EE / TE; tile += gridDim.x) {
        const int e0 = tile * TE;

        // phase 1: build feat = [edge_attr(16) | time_pe(8)] + edge metadata
        for (int idx = tid; idx < TE * 24; idx += NT) {
            int el = idx / 24, f = idx % 24;
            int e = e0 + el;
            float val;
            if (f < 16) val = edge_attr[(long long)e * 16 + f];
            else        val = fmaf(edge_time[e], Wt[f - 16], bt[f - 16]);
            S.feat[el * 24 + f] = val;
        }
        if (tid < TE) {
            int e = e0 + tid;
            S.s_src[tid] = ei[e];
            S.s_dst[tid] = ei[EE + e];
            int c = e / STEPC;
            S.s_att[2 * tid]     = g_p[2 * e]     / g_sum[2 * c];
            S.s_att[2 * tid + 1] = g_p[2 * e + 1] / g_sum[2 * c + 1];
        }
        __syncthreads();

        // phase 2: hmid = relu(W1 @ feat + b1), [TE x 82]; each warp: 4 edges
        {
            float acc[3][4];
#pragma unroll
            for (int m = 0; m < 3; m++) {
                int r = tx + 32 * m;
                float bb = (r < DK_) ? S.b1s[r] : 0.0f;
#pragma unroll
                for (int i = 0; i < 4; i++) acc[m][i] = bb;
            }
            const int r2 = (tx + 64 < DK_) ? (tx + 64) : 0;
#pragma unroll 4
            for (int f = 0; f < 24; f++) {
                float w0  = S.W1t[f * DK_ + tx];
                float w1  = S.W1t[f * DK_ + tx + 32];
                float w2v = S.W1t[f * DK_ + r2];
#pragma unroll
                for (int i = 0; i < 4; i++) {
                    float h = S.feat[(warp + 16 * i) * 24 + f];
                    acc[0][i] = fmaf(w0,  h, acc[0][i]);
                    acc[1][i] = fmaf(w1,  h, acc[1][i]);
                    acc[2][i] = fmaf(w2v, h, acc[2][i]);
                }
            }
#pragma unroll
            for (int m = 0; m < 3; m++) {
                int r = tx + 32 * m;
                if (r < DK_) {
#pragma unroll
                    for (int i = 0; i < 4; i++)
                        S.hmid[(warp + 16 * i) * DK_ + r] = fmaxf(acc[m][i], 0.0f);
                }
            }
        }
        __syncthreads();

        // phase 3a: async-prefetch the tile's v rows into Sm (hidden by k-loop)
        for (int idx = tid; idx < TE * NQ4; idx += NT) {
            int el = idx / NQ4, c4 = idx % NQ4;
            const float* src = v + (long long)S.s_src[el] * DD + c4 * 4;
            cp_async16(smSm + idx * 16, src);   // dst offset = el*656 + c4*16
        }
        asm volatile("cp.async.commit_group;" ::: "memory");

        // phase 3b: gb = W2 @ hmid + b2 as (gamma,beta)-paired f32x2 GEMM
        // warp covers m-slots [3*mh, 3*mh+3) x edges [elb, elb+8)
        {
            unsigned long long acc2[3][8];
#pragma unroll
            for (int mm = 0; mm < 3; mm++) {
                int mg = 3 * mh + mm;
                int d  = tx + 32 * mg;
                int dd = (d < DD) ? d : 0;
                float2 bb = S.b2p[dd];
                unsigned long long bp = pack2(bb.x, bb.y);
#pragma unroll
                for (int i = 0; i < 8; i++) acc2[mm][i] = bp;
            }
            const int dA = tx + 32 * (3 * mh + 0);
            const int dB = tx + 32 * (3 * mh + 1);
            const int dCr = tx + 32 * (3 * mh + 2);
            const int dC = (dCr < DD) ? dCr : 0;          // mh=1,tx>=4 dummy

            for (int kk = 0; kk < DK_; kk += 2) {
                unsigned long long hp0[8], hp1[8];
#pragma unroll
                for (int i = 0; i < 8; i++) {
                    float2 h2 = *reinterpret_cast<const float2*>(
                        &S.hmid[(elb + i) * DK_ + kk]);      // broadcast LDS.64
                    hp0[i] = dup2(h2.x);
                    hp1[i] = dup2(h2.y);
                }
                const unsigned long long* w0row =
                    reinterpret_cast<const unsigned long long*>(&S.W2p[kk * DD]);
                const unsigned long long* w1row =
                    reinterpret_cast<const unsigned long long*>(&S.W2p[(kk + 1) * DD]);
                unsigned long long wA0 = w0row[dA], wA1 = w1row[dA];
                unsigned long long wB0 = w0row[dB], wB1 = w1row[dB];
                unsigned long long wC0 = w0row[dC], wC1 = w1row[dC];
#pragma unroll
                for (int i = 0; i < 8; i++) {
                    FMA2(acc2[0][i], wA0, hp0[i]);
                    FMA2(acc2[1][i], wB0, hp0[i]);
                    FMA2(acc2[2][i], wC0, hp0[i]);
                    FMA2(acc2[0][i], wA1, hp1[i]);
                    FMA2(acc2[1][i], wB1, hp1[i]);
                    FMA2(acc2[2][i], wC1, hp1[i]);
                }
            }

            // v prefetch must be complete (own groups + everyone else's)
            asm volatile("cp.async.wait_group 0;" ::: "memory");
            __syncthreads();

            // epilogue: tanh, v-modulation (v read from Sm, in-place), att -> Sm
#pragma unroll
            for (int i = 0; i < 8; i++) {
                const int el = elb + i;
                const float a0 = S.s_att[2 * el];
                const float a1 = S.s_att[2 * el + 1];
#pragma unroll
                for (int mm = 0; mm < 3; mm++) {
                    int d = tx + 32 * (3 * mh + mm);
                    if (d < DD) {
                        float2 gb = unpack2(acc2[mm][i]);
                        float ga = fast_tanh(gb.x);
                        float be = fast_tanh(gb.y);
                        float att = (d < DK_) ? a0 : a1;
                        float vv = S.Sm[el * DD + d];
                        S.Sm[el * DD + d] = att * fmaf(vv, 1.0f + ga, be);
                    }
                }
            }
        }
        __syncthreads();

        // phase 4: vectorized scatter-add to out[dst]
        for (int idx = tid; idx < TE * NQ4; idx += NT) {
            int el = idx / NQ4, c4 = idx % NQ4;
            int dN = S.s_dst[el];
            float4 val = *reinterpret_cast<const float4*>(&S.Sm[el * DD + c4 * 4]);
            float* p = out + (long long)dN * DD + c4 * 4;
            asm volatile("red.global.add.v4.f32 [%0], {%1, %2, %3, %4};"
                         :: "l"(p), "f"(val.x), "f"(val.y), "f"(val.z), "f"(val.w)
                         : "memory");
        }
        __syncthreads();
    }
}

extern "C" void kernel_launch(void* const* d_in, const int* in_sizes, int n_in,
                              void* d_out, int out_size) {
    const float* q         = (const float*)d_in[0];
    const float* k         = (const float*)d_in[1];
    const float* v         = (const float*)d_in[2];
    const int*   ei        = (const int*)  d_in[3];
    const float* edge_attr = (const float*)d_in[4];
    const float* edge_time = (const float*)d_in[5];
    const float* Wt        = (const float*)d_in[6];
    const float* bt        = (const float*)d_in[7];
    const float* W1        = (const float*)d_in[8];
    const float* b1        = (const float*)d_in[9];
    const float* W2        = (const float*)d_in[10];
    const float* b2        = (const float*)d_in[11];
    const float* rb        = (const float*)d_in[12];
    float* out = (float*)d_out;

    cudaMemsetAsync(d_out, 0, (size_t)out_size * sizeof(float), 0);
    init_scratch_kernel<<<1, 64>>>();
    score_kernel<<<1184, 256>>>(q, k, ei, rb);
    expsum_kernel<<<1184, 256>>>();

    const int smem_bytes = (int)sizeof(Smem);
    cudaFuncSetAttribute(film_attn_kernel,
                         cudaFuncAttributeMaxDynamicSharedMemorySize, smem_bytes);
    film_attn_kernel<<<152, NT, smem_bytes>>>(ei, edge_attr, edge_time, Wt, bt,
                                              W1, b1, W2, b2, v, out);
}

// round 11
// speedup vs baseline: 2.2398x; 1.2496x over previous
#include <cuda_runtime.h>
#include <cuda_bf16.h>

// Problem constants (fixed by the dataset)
#define NN   100000
#define EE   600000
#define DD   164
#define HH   2
#define DK_  82
#define STEPC 30000
#define NC   20          // EE / STEPC
#define TE   64          // edges per tile in the fused kernel
#define NQ4  41          // DD/4 float4 chunks per row

static __device__ float    g_p[EE * 2];      // scores, then probs
static __device__ unsigned g_maxo[NC * 2];   // ordered-encoded per-chunk-per-head max
static __device__ float    g_sum[NC * 2];    // per-chunk-per-head exp sums

#define INV_SQRT_DK 0.11043152607484654f

// ---------- helpers ----------
__device__ __forceinline__ unsigned fenc(float f) {
    unsigned u = __float_as_uint(f);
    return u ^ ((unsigned)((int)u >> 31) | 0x80000000u);
}
__device__ __forceinline__ float fdec(unsigned u) {
    return __uint_as_float(u ^ ((unsigned)((~(int)u) >> 31) | 0x80000000u));
}
__device__ __forceinline__ unsigned long long pack2(float a, float b) {
    unsigned long long r;
    asm("mov.b64 %0, {%1, %2};" : "=l"(r) : "f"(a), "f"(b));
    return r;
}
__device__ __forceinline__ unsigned long long dup2(float a) {
    unsigned long long r;
    asm("mov.b64 %0, {%1, %1};" : "=l"(r) : "f"(a));
    return r;
}
__device__ __forceinline__ float2 unpack2(unsigned long long x) {
    float2 r;
    asm("mov.b64 {%0, %1}, %2;" : "=f"(r.x), "=f"(r.y) : "l"(x));
    return r;
}
#define FMA2(acc, a, b) \
    asm("fma.rn.f32x2 %0, %1, %2, %0;" : "+l"(acc) : "l"(a), "l"(b))

__device__ __forceinline__ float tanh_fast(float x) {
    float y;
    asm("tanh.approx.f32 %0, %1;" : "=f"(y) : "f"(x));
    return y;
}

__device__ __forceinline__ void cp_async16(unsigned smem_dst, const void* gsrc) {
    asm volatile("cp.async.ca.shared.global [%0], [%1], 16;"
                 :: "r"(smem_dst), "l"(gsrc) : "memory");
}

// ---------- kernel 0: reset scratch ----------
__global__ void init_scratch_kernel() {
    int i = threadIdx.x;
    if (i < NC * 2) { g_maxo[i] = 0u; g_sum[i] = 0.0f; }
}

// ---------- kernel 1: scores + per-chunk max (vectorized rows) ----------
// Row has 41 float4 chunks: lanes 0..31 take chunks 0..31 (d 0..127);
// lanes 0..8 additionally take chunks 32..40 (d 128..163, all head 1).
__global__ void score_kernel(const float* __restrict__ q, const float* __restrict__ k,
                             const int* __restrict__ ei, const float* __restrict__ rb) {
    __shared__ unsigned smax[NC * 2];
    for (int i = threadIdx.x; i < NC * 2; i += blockDim.x) smax[i] = 0u;
    __syncthreads();

    const float rb0 = rb[0], rb1 = rb[1];
    const int lane  = threadIdx.x & 31;
    const int gwarp = (blockIdx.x * blockDim.x + threadIdx.x) >> 5;
    const int nw    = (gridDim.x * blockDim.x) >> 5;

    for (int e = gwarp; e < EE; e += nw) {
        const int sN = ei[e];
        const int dN = ei[EE + e];
        const float* qr = q + (long long)dN * DD;
        const float* kr = k + (long long)sN * DD;
        float s0 = 0.0f, s1 = 0.0f;
        {
            const float4 q4 = *reinterpret_cast<const float4*>(qr + lane * 4);
            const float4 k4 = *reinterpret_cast<const float4*>(kr + lane * 4);
            float px = q4.x * k4.x, py = q4.y * k4.y, pz = q4.z * k4.z, pw = q4.w * k4.w;
            float all = (px + py) + (pz + pw);
            if (lane < 20)      { s0 = all; }
            else if (lane == 20){ s0 = px + py; s1 = pz + pw; }   // d 80,81 | 82,83
            else                { s1 = all; }
        }
        if (lane < 9) {   // chunks 32..40 -> d 128..163, entirely head 1
            const float4 q4 = *reinterpret_cast<const float4*>(qr + 128 + lane * 4);
            const float4 k4 = *reinterpret_cast<const float4*>(kr + 128 + lane * 4);
            s1 += (q4.x * k4.x + q4.y * k4.y) + (q4.z * k4.z + q4.w * k4.w);
        }
#pragma unroll
        for (int o = 16; o; o >>= 1) {
            s0 += __shfl_xor_sync(0xffffffffu, s0, o);
            s1 += __shfl_xor_sync(0xffffffffu, s1, o);
        }
        if (lane == 0) {
            float sc0 = fmaf(s0, INV_SQRT_DK, rb0);
            float sc1 = fmaf(s1, INV_SQRT_DK, rb1);
            g_p[2 * e]     = sc0;
            g_p[2 * e + 1] = sc1;
            int c = e / STEPC;
            atomicMax(&smax[2 * c],     fenc(sc0));
            atomicMax(&smax[2 * c + 1], fenc(sc1));
        }
    }
    __syncthreads();
    for (int i = threadIdx.x; i < NC * 2; i += blockDim.x)
        if (smax[i]) atomicMax(&g_maxo[i], smax[i]);
}

// ---------- kernel 2: exp + per-chunk sums ----------
__global__ void expsum_kernel() {
    __shared__ float ssum[NC * 2];
    for (int i = threadIdx.x; i < NC * 2; i += blockDim.x) ssum[i] = 0.0f;
    __syncthreads();

    const int gtid = blockIdx.x * blockDim.x + threadIdx.x;
    const int nt   = gridDim.x * blockDim.x;
    for (int e = gtid; e < EE; e += nt) {
        int c = e / STEPC;
        float m0 = fdec(g_maxo[2 * c]);
        float m1 = fdec(g_maxo[2 * c + 1]);
        float p0 = __expf(g_p[2 * e]     - m0);
        float p1 = __expf(g_p[2 * e + 1] - m1);
        g_p[2 * e]     = p0;
        g_p[2 * e + 1] = p1;
        atomicAdd(&ssum[2 * c],     p0);
        atomicAdd(&ssum[2 * c + 1], p1);
    }
    __syncthreads();
    for (int i = threadIdx.x; i < NC * 2; i += blockDim.x)
        if (ssum[i] != 0.0f) atomicAdd(&g_sum[i], ssum[i]);
}

// ---------- kernel 3: fused FiLM MLP + att * modulated-v + scatter ----------
// 512 threads / 16 warps. Phase-3 split: warp = (edge-group ew = warp>>1, d-half mh = warp&1).
// v rows AND next tile's raw inputs are prefetched via cp.async during the k-loop.
struct Smem {
    float2 W2p[DK_ * DD];       // [k][d]: (W2[d,k], W2[d+164,k])   107584 B
    float  W1t[24 * DK_];       // [f][r]                             7872 B
    float  b1s[DK_];            // 328 B
    float2 b2p[DD];             // (b2[d], b2[d+164])                 1312 B
    float  feat[TE * 24];       // 6144 B
    float  hmid[TE * DK_];      // 20992 B
    alignas(16) float Sm[TE * DD];   // 41984 B (v prefetch, then output staging)
    // prefetched raw inputs for next tile (cp.async targets, 16B-aligned)
    alignas(16) float raw_attr[TE * 16];   // 4096 B
    alignas(16) float raw_time[TE];        // 256 B
    alignas(16) int   raw_src[TE];
    alignas(16) int   raw_dst[TE];
    alignas(16) float raw_p[TE * 2];       // 512 B
    // stable per-tile copies (survive the next-tile prefetch overwrite)
    int    s_src[TE];
    int    s_dst[TE];
    float  s_att[TE * 2];       // (a0, a1) per edge
    float  s_invsum[NC * 2];
    float  sWt[8], sbt[8];
};

#define NT 512

__device__ __forceinline__ void prefetch_raw(Smem& S, int e0,
                                             const int* ei, const float* edge_attr,
                                             const float* edge_time, int tid) {
    // edge_attr: 64 edges x 64B = 256 x 16B
    for (int i = tid; i < 256; i += NT)
        cp_async16((unsigned)__cvta_generic_to_shared(&S.raw_attr[0]) + i * 16,
                   edge_attr + (long long)e0 * 16 + i * 4);
    if (tid < 16)
        cp_async16((unsigned)__cvta_generic_to_shared(&S.raw_time[0]) + tid * 16,
                   edge_time + e0 + tid * 4);
    else if (tid < 32) {
        int i = tid - 16;
        cp_async16((unsigned)__cvta_generic_to_shared(&S.raw_src[0]) + i * 16,
                   ei + e0 + i * 4);
    } else if (tid < 48) {
        int i = tid - 32;
        cp_async16((unsigned)__cvta_generic_to_shared(&S.raw_dst[0]) + i * 16,
                   ei + EE + e0 + i * 4);
    } else if (tid < 80) {
        int i = tid - 48;
        cp_async16((unsigned)__cvta_generic_to_shared(&S.raw_p[0]) + i * 16,
                   g_p + 2 * e0 + i * 4);
    }
}

__global__ void __launch_bounds__(NT, 1)
film_attn_kernel(const int* __restrict__ ei, const float* __restrict__ edge_attr,
                 const float* __restrict__ edge_time, const float* __restrict__ Wt,
                 const float* __restrict__ bt, const float* __restrict__ W1,
                 const float* __restrict__ b1, const float* __restrict__ W2,
                 const float* __restrict__ b2, const float* __restrict__ v,
                 float* __restrict__ out) {
    extern __shared__ char sraw[];
    Smem& S = *reinterpret_cast<Smem*>(sraw);
    const int tid = threadIdx.x;

    // stage weights (coalesced gmem reads, one-time)
    for (int idx = tid; idx < 328 * DK_; idx += NT) {
        int g = idx / DK_, kk = idx % DK_;
        float w = W2[idx];
        int d = (g < DD) ? g : g - DD;
        float* base = reinterpret_cast<float*>(&S.W2p[kk * DD + d]);
        base[(g < DD) ? 0 : 1] = w;
    }
    for (int idx = tid; idx < DK_ * 24; idx += NT) {
        int r = idx / 24, f = idx % 24;
        S.W1t[f * DK_ + r] = W1[idx];
    }
    for (int idx = tid; idx < DK_; idx += NT) S.b1s[idx] = b1[idx];
    for (int idx = tid; idx < DD; idx += NT)
        S.b2p[idx] = make_float2(b2[idx], b2[idx + DD]);
    if (tid < NC * 2) S.s_invsum[tid] = 1.0f / g_sum[tid];
    else if (tid < NC * 2 + 8)  S.sWt[tid - NC * 2] = Wt[tid - NC * 2];
    else if (tid < NC * 2 + 16) S.sbt[tid - NC * 2 - 8] = bt[tid - NC * 2 - 8];

    const int tx   = tid & 31;
    const int warp = tid >> 5;        // 0..15
    const int mh   = warp & 1;        // d-half: m-slots {0,1,2} or {3,4,5}
    const int ew   = warp >> 1;       // 0..7, edge group of 8
    const int elb  = ew * 8;
    const unsigned smSm = (unsigned)__cvta_generic_to_shared(&S.Sm[0]);
    const int tile_stride = gridDim.x;

    // prologue: prefetch the first tile's raw inputs
    prefetch_raw(S, blockIdx.x * TE, ei, edge_attr, edge_time, tid);
    asm volatile("cp.async.commit_group;" ::: "memory");

    for (int tile = blockIdx.x; tile < EE / TE; tile += tile_stride) {
        const int e0 = tile * TE;

        // raw inputs for this tile must have landed (prologue or previous wait)
        asm volatile("cp.async.wait_group 0;" ::: "memory");
        __syncthreads();

        // phase 1: build feat = [edge_attr(16) | time_pe(8)] + edge metadata (all smem)
        for (int idx = tid; idx < TE * 24; idx += NT) {
            int el = idx / 24, f = idx % 24;
            float val;
            if (f < 16) val = S.raw_attr[el * 16 + f];
            else        val = fmaf(S.raw_time[el], S.sWt[f - 16], S.sbt[f - 16]);
            S.feat[el * 24 + f] = val;
        }
        if (tid < TE) {
            S.s_src[tid] = S.raw_src[tid];
            S.s_dst[tid] = S.raw_dst[tid];
            int c = (e0 + tid) / STEPC;
            S.s_att[2 * tid]     = S.raw_p[2 * tid]     * S.s_invsum[2 * c];
            S.s_att[2 * tid + 1] = S.raw_p[2 * tid + 1] * S.s_invsum[2 * c + 1];
        }
        __syncthreads();

        // phase 2: hmid = relu(W1 @ feat + b1), [TE x 82]; each warp: 4 edges
        {
            float acc[3][4];
#pragma unroll
            for (int m = 0; m < 3; m++) {
                int r = tx + 32 * m;
                float bb = (r < DK_) ? S.b1s[r] : 0.0f;
#pragma unroll
                for (int i = 0; i < 4; i++) acc[m][i] = bb;
            }
            const int r2 = (tx + 64 < DK_) ? (tx + 64) : 0;
#pragma unroll 4
            for (int f = 0; f < 24; f++) {
                float w0  = S.W1t[f * DK_ + tx];
                float w1  = S.W1t[f * DK_ + tx + 32];
                float w2v = S.W1t[f * DK_ + r2];
#pragma unroll
                for (int i = 0; i < 4; i++) {
                    float h = S.feat[(warp + 16 * i) * 24 + f];
                    acc[0][i] = fmaf(w0,  h, acc[0][i]);
                    acc[1][i] = fmaf(w1,  h, acc[1][i]);
                    acc[2][i] = fmaf(w2v, h, acc[2][i]);
                }
            }
#pragma unroll
            for (int m = 0; m < 3; m++) {
                int r = tx + 32 * m;
                if (r < DK_) {
#pragma unroll
                    for (int i = 0; i < 4; i++)
                        S.hmid[(warp + 16 * i) * DK_ + r] = fmaxf(acc[m][i], 0.0f);
                }
            }
        }
        __syncthreads();

        // phase 3a: async-prefetch this tile's v rows into Sm + next tile's raw inputs
        for (int idx = tid; idx < TE * NQ4; idx += NT) {
            int el = idx / NQ4, c4 = idx % NQ4;
            const float* src = v + (long long)S.s_src[el] * DD + c4 * 4;
            cp_async16(smSm + idx * 16, src);   // dst offset = el*656 + c4*16
        }
        {
            int ntile = tile + tile_stride;
            if (ntile < EE / TE)
                prefetch_raw(S, ntile * TE, ei, edge_attr, edge_time, tid);
        }
        asm volatile("cp.async.commit_group;" ::: "memory");

        // phase 3b: gb = W2 @ hmid + b2 as (gamma,beta)-paired f32x2 GEMM
        // warp covers m-slots [3*mh, 3*mh+3) x edges [elb, elb+8)
        {
            unsigned long long acc2[3][8];
#pragma unroll
            for (int mm = 0; mm < 3; mm++) {
                int mg = 3 * mh + mm;
                int d  = tx + 32 * mg;
                int dd = (d < DD) ? d : 0;
                float2 bb = S.b2p[dd];
                unsigned long long bp = pack2(bb.x, bb.y);
#pragma unroll
                for (int i = 0; i < 8; i++) acc2[mm][i] = bp;
            }
            const int dA = tx + 32 * (3 * mh + 0);
            const int dB = tx + 32 * (3 * mh + 1);
            const int dCr = tx + 32 * (3 * mh + 2);
            const int dC = (dCr < DD) ? dCr : 0;          // mh=1,tx>=4 dummy

            for (int kk = 0; kk < DK_; kk += 2) {
                unsigned long long hp0[8], hp1[8];
#pragma unroll
                for (int i = 0; i < 8; i++) {
                    float2 h2 = *reinterpret_cast<const float2*>(
                        &S.hmid[(elb + i) * DK_ + kk]);      // broadcast LDS.64
                    hp0[i] = dup2(h2.x);
                    hp1[i] = dup2(h2.y);
                }
                const unsigned long long* w0row =
                    reinterpret_cast<const unsigned long long*>(&S.W2p[kk * DD]);
                const unsigned long long* w1row =
                    reinterpret_cast<const unsigned long long*>(&S.W2p[(kk + 1) * DD]);
                unsigned long long wA0 = w0row[dA], wA1 = w1row[dA];
                unsigned long long wB0 = w0row[dB], wB1 = w1row[dB];
                unsigned long long wC0 = w0row[dC], wC1 = w1row[dC];
#pragma unroll
                for (int i = 0; i < 8; i++) {
                    FMA2(acc2[0][i], wA0, hp0[i]);
                    FMA2(acc2[1][i], wB0, hp0[i]);
                    FMA2(acc2[2][i], wC0, hp0[i]);
                    FMA2(acc2[0][i], wA1, hp1[i]);
                    FMA2(acc2[1][i], wB1, hp1[i]);
                    FMA2(acc2[2][i], wC1, hp1[i]);
                }
            }

            // v prefetch (and next-tile raw) must be complete
            asm volatile("cp.async.wait_group 0;" ::: "memory");
            __syncthreads();

            // epilogue: tanh.approx, v-modulation (v read from Sm, in-place), att -> Sm
#pragma unroll
            for (int i = 0; i < 8; i++) {
                const int el = elb + i;
                const float a0 = S.s_att[2 * el];
                const float a1 = S.s_att[2 * el + 1];
#pragma unroll
                for (int mm = 0; mm < 3; mm++) {
                    int d = tx + 32 * (3 * mh + mm);
                    if (d < DD) {
                        float2 gb = unpack2(acc2[mm][i]);
                        float ga = tanh_fast(gb.x);
                        float be = tanh_fast(gb.y);
                        float att = (d < DK_) ? a0 : a1;
                        float vv = S.Sm[el * DD + d];
                        S.Sm[el * DD + d] = att * fmaf(vv, 1.0f + ga, be);
                    }
                }
            }
        }
        __syncthreads();

        // phase 4: vectorized scatter-add to out[dst]
        for (int idx = tid; idx < TE * NQ4; idx += NT) {
            int el = idx / NQ4, c4 = idx % NQ4;
            int dN = S.s_dst[el];
            float4 val = *reinterpret_cast<const float4*>(&S.Sm[el * DD + c4 * 4]);
            float* p = out + (long long)dN * DD + c4 * 4;
            asm volatile("red.global.add.v4.f32 [%0], {%1, %2, %3, %4};"
                         :: "l"(p), "f"(val.x), "f"(val.y), "f"(val.z), "f"(val.w)
                         : "memory");
        }
        __syncthreads();
    }
}

extern "C" void kernel_launch(void* const* d_in, const int* in_sizes, int n_in,
                              void* d_out, int out_size) {
    const float* q         = (const float*)d_in[0];
    const float* k         = (const float*)d_in[1];
    const float* v         = (const float*)d_in[2];
    const int*   ei        = (const int*)  d_in[3];
    const float* edge_attr = (const float*)d_in[4];
    const float* edge_time = (const float*)d_in[5];
    const float* Wt        = (const float*)d_in[6];
    const float* bt        = (const float*)d_in[7];
    const float* W1        = (const float*)d_in[8];
    const float* b1        = (const float*)d_in[9];
    const float* W2        = (const float*)d_in[10];
    const float* b2        = (const float*)d_in[11];
    const float* rb        = (const float*)d_in[12];
    float* out = (float*)d_out;

    cudaMemsetAsync(d_out, 0, (size_t)out_size * sizeof(float), 0);
    init_scratch_kernel<<<1, 64>>>();
    score_kernel<<<1184, 256>>>(q, k, ei, rb);
    expsum_kernel<<<1184, 256>>>();

    const int smem_bytes = (int)sizeof(Smem);
    cudaFuncSetAttribute(film_attn_kernel,
                         cudaFuncAttributeMaxDynamicSharedMemorySize, smem_bytes);
    film_attn_kernel<<<152, NT, smem_bytes>>>(ei, edge_attr, edge_time, Wt, bt,
                                              W1, b1, W2, b2, v, out);
}

// round 12
// speedup vs baseline: 3.9365x; 1.7575x over previous
#include <cuda_runtime.h>
#include <cuda_bf16.h>

// Problem constants (fixed by the dataset)
#define NN   100000
#define EE   600000
#define DD   164
#define HH   2
#define DK_  82
#define STEPC 30000
#define NC   20          // EE / STEPC
#define TE   64          // edges per tile in the fused kernel
#define NQ4  41          // DD/4 float4 chunks per row

#define KT2  6           // k padded to 96 -> 12 k8-tiles -> 6 pairs
#define NTT  44          // n8-tiles over gamma/beta-interleaved 352 cols (164*2 pad)

static __device__ float    g_p[EE * 2];      // scores, then probs
static __device__ unsigned g_maxo[NC * 2];   // ordered-encoded per-chunk-per-head max
static __device__ float    g_sum[NC * 2];    // per-chunk-per-head exp sums

#define INV_SQRT_DK 0.11043152607484654f

// ---------- helpers ----------
__device__ __forceinline__ unsigned fenc(float f) {
    unsigned u = __float_as_uint(f);
    return u ^ ((unsigned)((int)u >> 31) | 0x80000000u);
}
__device__ __forceinline__ float fdec(unsigned u) {
    return __uint_as_float(u ^ ((unsigned)((~(int)u) >> 31) | 0x80000000u));
}
__device__ __forceinline__ float tanh_fast(float x) {
    float y;
    asm("tanh.approx.f32 %0, %1;" : "=f"(y) : "f"(x));
    return y;
}
__device__ __forceinline__ unsigned to_tf32(float f) {
    unsigned u;
    asm("cvt.rna.tf32.f32 %0, %1;" : "=r"(u) : "f"(f));
    return u;
}
__device__ __forceinline__ void cp_async16(unsigned smem_dst, const void* gsrc) {
    asm volatile("cp.async.ca.shared.global [%0], [%1], 16;"
                 :: "r"(smem_dst), "l"(gsrc) : "memory");
}
__device__ __forceinline__ void mma_tf32(float* c, unsigned a0, unsigned a1,
                                         unsigned a2, unsigned a3,
                                         unsigned b0, unsigned b1) {
    asm volatile("mma.sync.aligned.m16n8k8.row.col.f32.tf32.tf32.f32 "
                 "{%0,%1,%2,%3}, {%4,%5,%6,%7}, {%8,%9}, {%0,%1,%2,%3};"
                 : "+f"(c[0]), "+f"(c[1]), "+f"(c[2]), "+f"(c[3])
                 : "r"(a0), "r"(a1), "r"(a2), "r"(a3), "r"(b0), "r"(b1));
}

// ---------- kernel 0: reset scratch ----------
__global__ void init_scratch_kernel() {
    int i = threadIdx.x;
    if (i < NC * 2) { g_maxo[i] = 0u; g_sum[i] = 0.0f; }
}

// ---------- kernel 1: scores + per-chunk max (vectorized rows) ----------
__global__ void score_kernel(const float* __restrict__ q, const float* __restrict__ k,
                             const int* __restrict__ ei, const float* __restrict__ rb) {
    __shared__ unsigned smax[NC * 2];
    for (int i = threadIdx.x; i < NC * 2; i += blockDim.x) smax[i] = 0u;
    __syncthreads();

    const float rb0 = rb[0], rb1 = rb[1];
    const int lane  = threadIdx.x & 31;
    const int gwarp = (blockIdx.x * blockDim.x + threadIdx.x) >> 5;
    const int nw    = (gridDim.x * blockDim.x) >> 5;

    for (int e = gwarp; e < EE; e += nw) {
        const int sN = ei[e];
        const int dN = ei[EE + e];
        const float* qr = q + (long long)dN * DD;
        const float* kr = k + (long long)sN * DD;
        float s0 = 0.0f, s1 = 0.0f;
        {
            const float4 q4 = *reinterpret_cast<const float4*>(qr + lane * 4);
            const float4 k4 = *reinterpret_cast<const float4*>(kr + lane * 4);
            float px = q4.x * k4.x, py = q4.y * k4.y, pz = q4.z * k4.z, pw = q4.w * k4.w;
            float all = (px + py) + (pz + pw);
            if (lane < 20)      { s0 = all; }
            else if (lane == 20){ s0 = px + py; s1 = pz + pw; }   // d 80,81 | 82,83
            else                { s1 = all; }
        }
        if (lane < 9) {   // chunks 32..40 -> d 128..163, entirely head 1
            const float4 q4 = *reinterpret_cast<const float4*>(qr + 128 + lane * 4);
            const float4 k4 = *reinterpret_cast<const float4*>(kr + 128 + lane * 4);
            s1 += (q4.x * k4.x + q4.y * k4.y) + (q4.z * k4.z + q4.w * k4.w);
        }
#pragma unroll
        for (int o = 16; o; o >>= 1) {
            s0 += __shfl_xor_sync(0xffffffffu, s0, o);
            s1 += __shfl_xor_sync(0xffffffffu, s1, o);
        }
        if (lane == 0) {
            float sc0 = fmaf(s0, INV_SQRT_DK, rb0);
            float sc1 = fmaf(s1, INV_SQRT_DK, rb1);
            g_p[2 * e]     = sc0;
            g_p[2 * e + 1] = sc1;
            int c = e / STEPC;
            atomicMax(&smax[2 * c],     fenc(sc0));
            atomicMax(&smax[2 * c + 1], fenc(sc1));
        }
    }
    __syncthreads();
    for (int i = threadIdx.x; i < NC * 2; i += blockDim.x)
        if (smax[i]) atomicMax(&g_maxo[i], smax[i]);
}

// ---------- kernel 2: exp + per-chunk sums ----------
__global__ void expsum_kernel() {
    __shared__ float ssum[NC * 2];
    for (int i = threadIdx.x; i < NC * 2; i += blockDim.x) ssum[i] = 0.0f;
    __syncthreads();

    const int gtid = blockIdx.x * blockDim.x + threadIdx.x;
    const int nt   = gridDim.x * blockDim.x;
    for (int e = gtid; e < EE; e += nt) {
        int c = e / STEPC;
        float m0 = fdec(g_maxo[2 * c]);
        float m1 = fdec(g_maxo[2 * c + 1]);
        float p0 = __expf(g_p[2 * e]     - m0);
        float p1 = __expf(g_p[2 * e + 1] - m1);
        g_p[2 * e]     = p0;
        g_p[2 * e + 1] = p1;
        atomicAdd(&ssum[2 * c],     p0);
        atomicAdd(&ssum[2 * c + 1], p1);
    }
    __syncthreads();
    for (int i = threadIdx.x; i < NC * 2; i += blockDim.x)
        if (ssum[i] != 0.0f) atomicAdd(&g_sum[i], ssum[i]);
}

// ---------- kernel 3: fused FiLM MLP (tf32 tensor-core) + att*mod-v + scatter ----------
// 512 threads / 16 warps. Phase-3: mma.sync m16n8k8 tf32.
//   C[64 edges x 352 g'] where g' = 2d + h interleaves (gamma_d, beta_d) columns.
//   Warp = (mg = warp&1: m-tiles {2mg,2mg+1}) x (ng = warp>>1: 5-6 n-tiles of 44).
struct Smem {
    alignas(16) float w2f[NTT * KT2 * 32 * 4];        // B frags, 135168 B
    alignas(16) float hfrag[4 * KT2 * 2 * 32 * 4];    // A frags, 24576 B
    alignas(16) float Sm[TE * DD];                    // 41984 B (v prefetch -> output)
    float  feat[TE * 24];                             // 6144 B
    float  W1t[24 * DK_];                             // 7872 B
    float  b1s[DK_];
    float2 b2p[DD];                                   // (b2[d], b2[d+164])
    alignas(16) float raw_attr[TE * 16];
    alignas(16) float raw_time[TE];
    alignas(16) int   raw_src[TE];
    alignas(16) int   raw_dst[TE];
    alignas(16) float raw_p[TE * 2];
    int    s_src[TE];
    int    s_dst[TE];
    float  s_att[TE * 2];
    float  s_invsum[NC * 2];
    float  sWt[8], sbt[8];
};

#define NT 512

__device__ __forceinline__ void prefetch_raw(Smem& S, int e0,
                                             const int* ei, const float* edge_attr,
                                             const float* edge_time, int tid) {
    for (int i = tid; i < 256; i += NT)
        cp_async16((unsigned)__cvta_generic_to_shared(&S.raw_attr[0]) + i * 16,
                   edge_attr + (long long)e0 * 16 + i * 4);
    if (tid < 16)
        cp_async16((unsigned)__cvta_generic_to_shared(&S.raw_time[0]) + tid * 16,
                   edge_time + e0 + tid * 4);
    else if (tid < 32) {
        int i = tid - 16;
        cp_async16((unsigned)__cvta_generic_to_shared(&S.raw_src[0]) + i * 16,
                   ei + e0 + i * 4);
    } else if (tid < 48) {
        int i = tid - 32;
        cp_async16((unsigned)__cvta_generic_to_shared(&S.raw_dst[0]) + i * 16,
                   ei + EE + e0 + i * 4);
    } else if (tid < 80) {
        int i = tid - 48;
        cp_async16((unsigned)__cvta_generic_to_shared(&S.raw_p[0]) + i * 16,
                   g_p + 2 * e0 + i * 4);
    }
}

__global__ void __launch_bounds__(NT, 1)
film_attn_kernel(const int* __restrict__ ei, const float* __restrict__ edge_attr,
                 const float* __restrict__ edge_time, const float* __restrict__ Wt,
                 const float* __restrict__ bt, const float* __restrict__ W1,
                 const float* __restrict__ b1, const float* __restrict__ W2,
                 const float* __restrict__ b2, const float* __restrict__ v,
                 float* __restrict__ out) {
    extern __shared__ char sraw[];
    Smem& S = *reinterpret_cast<Smem*>(sraw);
    const int tid = threadIdx.x;

    // ---- prologue staging (once) ----
    // W2 -> B-fragment order, tf32-rounded, gamma/beta interleaved columns.
    // w2f[(nt*KT2 + kt2)*32 + lane] = float4{ b0@kt=2kt2, b1@kt=2kt2, b0@kt+1, b1@kt+1 }
    // b0@kt: k = 8kt + (lane&3), g' = 8nt + (lane>>2); b1: k+4.
    for (int idx = tid; idx < NTT * KT2 * 32; idx += NT) {
        int lane = idx & 31;
        int rest = idx >> 5;
        int kt2 = rest % KT2;
        int ntg = rest / KT2;
        int gp = 8 * ntg + (lane >> 2);
        int d  = gp >> 1, h = gp & 1;
        int kb = 16 * kt2 + (lane & 3);
        float4 val;
        if (d < DD) {
            const float* wrow = W2 + (long long)(d + DD * h) * DK_;
            val.x = (kb      < DK_) ? __uint_as_float(to_tf32(wrow[kb]))      : 0.0f;
            val.y = (kb + 4  < DK_) ? __uint_as_float(to_tf32(wrow[kb + 4]))  : 0.0f;
            val.z = (kb + 8  < DK_) ? __uint_as_float(to_tf32(wrow[kb + 8]))  : 0.0f;
            val.w = (kb + 12 < DK_) ? __uint_as_float(to_tf32(wrow[kb + 12])) : 0.0f;
        } else {
            val = make_float4(0.f, 0.f, 0.f, 0.f);
        }
        *reinterpret_cast<float4*>(&S.w2f[idx * 4]) = val;
    }
    // hfrag zero-fill (padded k slots stay zero forever; k<82 rewritten per tile)
    for (int i = tid; i < 4 * KT2 * 2 * 32; i += NT)
        *reinterpret_cast<float4*>(&S.hfrag[i * 4]) = make_float4(0.f, 0.f, 0.f, 0.f);
    for (int idx = tid; idx < DK_ * 24; idx += NT) {
        int r = idx / 24, f = idx % 24;
        S.W1t[f * DK_ + r] = W1[idx];
    }
    for (int idx = tid; idx < DK_; idx += NT) S.b1s[idx] = b1[idx];
    for (int idx = tid; idx < DD; idx += NT)
        S.b2p[idx] = make_float2(b2[idx], b2[idx + DD]);
    if (tid < NC * 2) S.s_invsum[tid] = 1.0f / g_sum[tid];
    else if (tid < NC * 2 + 8)  S.sWt[tid - NC * 2] = Wt[tid - NC * 2];
    else if (tid < NC * 2 + 16) S.sbt[tid - NC * 2 - 8] = bt[tid - NC * 2 - 8];

    const int tx   = tid & 31;
    const int warp = tid >> 5;        // 0..15
    const int mg   = warp & 1;        // m-group: m-tiles {2mg, 2mg+1}
    const int ng   = warp >> 1;       // 0..7
    const int ntbase = (ng < 4) ? 6 * ng : 24 + 5 * (ng - 4);
    const int ntcnt  = (ng < 4) ? 6 : 5;
    const unsigned smSm = (unsigned)__cvta_generic_to_shared(&S.Sm[0]);
    const int tile_stride = gridDim.x;

    prefetch_raw(S, blockIdx.x * TE, ei, edge_attr, edge_time, tid);
    asm volatile("cp.async.commit_group;" ::: "memory");

    for (int tile = blockIdx.x; tile < EE / TE; tile += tile_stride) {
        const int e0 = tile * TE;

        asm volatile("cp.async.wait_group 0;" ::: "memory");
        __syncthreads();

        // phase 1: feat + edge metadata (all smem)
        for (int idx = tid; idx < TE * 24; idx += NT) {
            int el = idx / 24, f = idx % 24;
            float val;
            if (f < 16) val = S.raw_attr[el * 16 + f];
            else        val = fmaf(S.raw_time[el], S.sWt[f - 16], S.sbt[f - 16]);
            S.feat[el * 24 + f] = val;
        }
        if (tid < TE) {
            S.s_src[tid] = S.raw_src[tid];
            S.s_dst[tid] = S.raw_dst[tid];
            int c = (e0 + tid) / STEPC;
            S.s_att[2 * tid]     = S.raw_p[2 * tid]     * S.s_invsum[2 * c];
            S.s_att[2 * tid + 1] = S.raw_p[2 * tid + 1] * S.s_invsum[2 * c + 1];
        }
        __syncthreads();

        // phase 2: hmid = relu(W1 @ feat + b1) -> tf32 -> A-fragment order
        {
            float acc[3][4];
#pragma unroll
            for (int m = 0; m < 3; m++) {
                int r = tx + 32 * m;
                float bb = (r < DK_) ? S.b1s[r] : 0.0f;
#pragma unroll
                for (int i = 0; i < 4; i++) acc[m][i] = bb;
            }
            const int r2 = (tx + 64 < DK_) ? (tx + 64) : 0;
#pragma unroll 4
            for (int f = 0; f < 24; f++) {
                float w0  = S.W1t[f * DK_ + tx];
                float w1  = S.W1t[f * DK_ + tx + 32];
                float w2v = S.W1t[f * DK_ + r2];
#pragma unroll
                for (int i = 0; i < 4; i++) {
                    float h = S.feat[(warp + 16 * i) * 24 + f];
                    acc[0][i] = fmaf(w0,  h, acc[0][i]);
                    acc[1][i] = fmaf(w1,  h, acc[1][i]);
                    acc[2][i] = fmaf(w2v, h, acc[2][i]);
                }
            }
            // store: edge el = warp + 16i (mt = i, frag row rl = warp), k-row r
#pragma unroll
            for (int m = 0; m < 3; m++) {
                int r = tx + 32 * m;
                if (r < DK_) {
                    int kt  = r >> 3, kc = r & 7;
                    int kt2 = kt >> 1, ktp = kt & 1;
                    int lane2 = ((warp & 7) << 2) | (kc & 3);
                    int slot  = ((warp >> 3) & 1) | (((kc >> 2) & 1) << 1);
#pragma unroll
                    for (int i = 0; i < 4; i++) {
                        unsigned t32 = to_tf32(fmaxf(acc[m][i], 0.0f));
                        S.hfrag[((((i * KT2 + kt2) * 2 + ktp) * 32 + lane2) << 2) | slot]
                            = __uint_as_float(t32);
                    }
                }
            }
        }
        __syncthreads();

        // phase 3a: async-prefetch v rows into Sm + next tile's raw inputs
        for (int idx = tid; idx < TE * NQ4; idx += NT) {
            int el = idx / NQ4, c4 = idx % NQ4;
            const float* src = v + (long long)S.s_src[el] * DD + c4 * 4;
            cp_async16(smSm + idx * 16, src);
        }
        {
            int ntile = tile + tile_stride;
            if (ntile < EE / TE)
                prefetch_raw(S, ntile * TE, ei, edge_attr, edge_time, tid);
        }
        asm volatile("cp.async.commit_group;" ::: "memory");

        // phase 3b: tf32 MMA  C[edges x g'] = hmid @ W2'  (+ b2 in C-init)
        {
            float c[2][6][4];
#pragma unroll
            for (int t = 0; t < 6; t++) {
                int d = 4 * (ntbase + t) + (tx & 3);
                int dd = (d < DD) ? d : 0;
                float2 bb = S.b2p[dd];
#pragma unroll
                for (int mtl = 0; mtl < 2; mtl++) {
                    c[mtl][t][0] = bb.x; c[mtl][t][1] = bb.y;
                    c[mtl][t][2] = bb.x; c[mtl][t][3] = bb.y;
                }
            }
#pragma unroll
            for (int kt2 = 0; kt2 < KT2; kt2++) {
                uint4 a[2][2];
#pragma unroll
                for (int mtl = 0; mtl < 2; mtl++) {
                    int mt = 2 * mg + mtl;
                    float4 f0 = *reinterpret_cast<const float4*>(
                        &S.hfrag[(((mt * KT2 + kt2) * 2 + 0) * 32 + tx) * 4]);
                    float4 f1 = *reinterpret_cast<const float4*>(
                        &S.hfrag[(((mt * KT2 + kt2) * 2 + 1) * 32 + tx) * 4]);
                    a[mtl][0] = make_uint4(__float_as_uint(f0.x), __float_as_uint(f0.y),
                                           __float_as_uint(f0.z), __float_as_uint(f0.w));
                    a[mtl][1] = make_uint4(__float_as_uint(f1.x), __float_as_uint(f1.y),
                                           __float_as_uint(f1.z), __float_as_uint(f1.w));
                }
#pragma unroll
                for (int t = 0; t < 6; t++) {
                    if (t < ntcnt) {
                        float4 b = *reinterpret_cast<const float4*>(
                            &S.w2f[(((ntbase + t) * KT2 + kt2) * 32 + tx) * 4]);
                        unsigned b0e = __float_as_uint(b.x), b1e = __float_as_uint(b.y);
                        unsigned b0o = __float_as_uint(b.z), b1o = __float_as_uint(b.w);
#pragma unroll
                        for (int mtl = 0; mtl < 2; mtl++) {
                            mma_tf32(c[mtl][t], a[mtl][0].x, a[mtl][0].y,
                                     a[mtl][0].z, a[mtl][0].w, b0e, b1e);
                            mma_tf32(c[mtl][t], a[mtl][1].x, a[mtl][1].y,
                                     a[mtl][1].z, a[mtl][1].w, b0o, b1o);
                        }
                    }
                }
            }

            asm volatile("cp.async.wait_group 0;" ::: "memory");
            __syncthreads();

            // epilogue: (c0,c1)=(gamma,beta) at el0, (c2,c3) at el0+8; in-register
#pragma unroll
            for (int t = 0; t < 6; t++) {
                if (t < ntcnt) {
                    int d = 4 * (ntbase + t) + (tx & 3);
                    if (d < DD) {
                        int h = (d >= DK_) ? 1 : 0;
#pragma unroll
                        for (int mtl = 0; mtl < 2; mtl++) {
                            int el0 = 32 * mg + 16 * mtl + (tx >> 2);
                            int el1 = el0 + 8;
                            float at0 = S.s_att[2 * el0 + h];
                            float at1 = S.s_att[2 * el1 + h];
                            float g0 = tanh_fast(c[mtl][t][0]);
                            float be0 = tanh_fast(c[mtl][t][1]);
                            float g1 = tanh_fast(c[mtl][t][2]);
                            float be1 = tanh_fast(c[mtl][t][3]);
                            float v0 = S.Sm[el0 * DD + d];
                            float v1 = S.Sm[el1 * DD + d];
                            S.Sm[el0 * DD + d] = at0 * fmaf(v0, 1.0f + g0, be0);
                            S.Sm[el1 * DD + d] = at1 * fmaf(v1, 1.0f + g1, be1);
                        }
                    }
                }
            }
        }
        __syncthreads();

        // phase 4: vectorized scatter-add to out[dst]
        for (int idx = tid; idx < TE * NQ4; idx += NT) {
            int el = idx / NQ4, c4 = idx % NQ4;
            int dN = S.s_dst[el];
            float4 val = *reinterpret_cast<const float4*>(&S.Sm[el * DD + c4 * 4]);
            float* p = out + (long long)dN * DD + c4 * 4;
            asm volatile("red.global.add.v4.f32 [%0], {%1, %2, %3, %4};"
                         :: "l"(p), "f"(val.x), "f"(val.y), "f"(val.z), "f"(val.w)
                         : "memory");
        }
        __syncthreads();
    }
}

extern "C" void kernel_launch(void* const* d_in, const int* in_sizes, int n_in,
                              void* d_out, int out_size) {
    const float* q         = (const float*)d_in[0];
    const float* k         = (const float*)d_in[1];
    const float* v         = (const float*)d_in[2];
    const int*   ei        = (const int*)  d_in[3];
    const float* edge_attr = (const float*)d_in[4];
    const float* edge_time = (const float*)d_in[5];
    const float* Wt        = (const float*)d_in[6];
    const float* bt        = (const float*)d_in[7];
    const float* W1        = (const float*)d_in[8];
    const float* b1        = (const float*)d_in[9];
    const float* W2        = (const float*)d_in[10];
    const float* b2        = (const float*)d_in[11];
    const float* rb        = (const float*)d_in[12];
    float* out = (float*)d_out;

    cudaMemsetAsync(d_out, 0, (size_t)out_size * sizeof(float), 0);
    init_scratch_kernel<<<1, 64>>>();
    score_kernel<<<1184, 256>>>(q, k, ei, rb);
    expsum_kernel<<<1184, 256>>>();

    const int smem_bytes = (int)sizeof(Smem);
    cudaFuncSetAttribute(film_attn_kernel,
                         cudaFuncAttributeMaxDynamicSharedMemorySize, smem_bytes);
    film_attn_kernel<<<152, NT, smem_bytes>>>(ei, edge_attr, edge_time, Wt, bt,
                                              W1, b1, W2, b2, v, out);
}

// round 13
// speedup vs baseline: 4.4420x; 1.1284x over previous
#include <cuda_runtime.h>
#include <cuda_bf16.h>

// Problem constants (fixed by the dataset)
#define NN   100000
#define EE   600000
#define DD   164
#define HH   2
#define DK_  82
#define STEPC 30000
#define NC   20          // EE / STEPC
#define TE   64          // edges per tile in the fused kernel
#define NQ4  41          // DD/4 float4 chunks per row

#define KT2  6           // k padded to 96 -> 12 k8-tiles -> 6 pairs
#define NTT  44          // n8-tiles over gamma/beta-interleaved 352 cols (164*2 pad)

static __device__ float    g_p[EE * 2];      // scores, then probs
static __device__ unsigned g_maxo[NC * 2];   // ordered-encoded per-chunk-per-head max
static __device__ float    g_sum[NC * 2];    // per-chunk-per-head exp sums

#define INV_SQRT_DK 0.11043152607484654f

// ---------- helpers ----------
__device__ __forceinline__ unsigned fenc(float f) {
    unsigned u = __float_as_uint(f);
    return u ^ ((unsigned)((int)u >> 31) | 0x80000000u);
}
__device__ __forceinline__ float fdec(unsigned u) {
    return __uint_as_float(u ^ ((unsigned)((~(int)u) >> 31) | 0x80000000u));
}
__device__ __forceinline__ float tanh_fast(float x) {
    float y;
    asm("tanh.approx.f32 %0, %1;" : "=f"(y) : "f"(x));
    return y;
}
__device__ __forceinline__ unsigned to_tf32(float f) {
    unsigned u;
    asm("cvt.rna.tf32.f32 %0, %1;" : "=r"(u) : "f"(f));
    return u;
}
__device__ __forceinline__ void cp_async16(unsigned smem_dst, const void* gsrc) {
    asm volatile("cp.async.ca.shared.global [%0], [%1], 16;"
                 :: "r"(smem_dst), "l"(gsrc) : "memory");
}
__device__ __forceinline__ void mma_tf32(float* c, unsigned a0, unsigned a1,
                                         unsigned a2, unsigned a3,
                                         unsigned b0, unsigned b1) {
    asm volatile("mma.sync.aligned.m16n8k8.row.col.f32.tf32.tf32.f32 "
                 "{%0,%1,%2,%3}, {%4,%5,%6,%7}, {%8,%9}, {%0,%1,%2,%3};"
                 : "+f"(c[0]), "+f"(c[1]), "+f"(c[2]), "+f"(c[3])
                 : "r"(a0), "r"(a1), "r"(a2), "r"(a3), "r"(b0), "r"(b1));
}

// ---------- kernel 0: reset scratch ----------
__global__ void init_scratch_kernel() {
    int i = threadIdx.x;
    if (i < NC * 2) { g_maxo[i] = 0u; g_sum[i] = 0.0f; }
}

// ---------- kernel 1: scores + per-chunk max (vectorized rows) ----------
__global__ void score_kernel(const float* __restrict__ q, const float* __restrict__ k,
                             const int* __restrict__ ei, const float* __restrict__ rb) {
    __shared__ unsigned smax[NC * 2];
    for (int i = threadIdx.x; i < NC * 2; i += blockDim.x) smax[i] = 0u;
    __syncthreads();

    const float rb0 = rb[0], rb1 = rb[1];
    const int lane  = threadIdx.x & 31;
    const int gwarp = (blockIdx.x * blockDim.x + threadIdx.x) >> 5;
    const int nw    = (gridDim.x * blockDim.x) >> 5;

    for (int e = gwarp; e < EE; e += nw) {
        const int sN = ei[e];
        const int dN = ei[EE + e];
        const float* qr = q + (long long)dN * DD;
        const float* kr = k + (long long)sN * DD;
        float s0 = 0.0f, s1 = 0.0f;
        {
            const float4 q4 = *reinterpret_cast<const float4*>(qr + lane * 4);
            const float4 k4 = *reinterpret_cast<const float4*>(kr + lane * 4);
            float px = q4.x * k4.x, py = q4.y * k4.y, pz = q4.z * k4.z, pw = q4.w * k4.w;
            float all = (px + py) + (pz + pw);
            if (lane < 20)      { s0 = all; }
            else if (lane == 20){ s0 = px + py; s1 = pz + pw; }   // d 80,81 | 82,83
            else                { s1 = all; }
        }
        if (lane < 9) {   // chunks 32..40 -> d 128..163, entirely head 1
            const float4 q4 = *reinterpret_cast<const float4*>(qr + 128 + lane * 4);
            const float4 k4 = *reinterpret_cast<const float4*>(kr + 128 + lane * 4);
            s1 += (q4.x * k4.x + q4.y * k4.y) + (q4.z * k4.z + q4.w * k4.w);
        }
#pragma unroll
        for (int o = 16; o; o >>= 1) {
            s0 += __shfl_xor_sync(0xffffffffu, s0, o);
            s1 += __shfl_xor_sync(0xffffffffu, s1, o);
        }
        if (lane == 0) {
            float sc0 = fmaf(s0, INV_SQRT_DK, rb0);
            float sc1 = fmaf(s1, INV_SQRT_DK, rb1);
            g_p[2 * e]     = sc0;
            g_p[2 * e + 1] = sc1;
            int c = e / STEPC;
            atomicMax(&smax[2 * c],     fenc(sc0));
            atomicMax(&smax[2 * c + 1], fenc(sc1));
        }
    }
    __syncthreads();
    for (int i = threadIdx.x; i < NC * 2; i += blockDim.x)
        if (smax[i]) atomicMax(&g_maxo[i], smax[i]);
}

// ---------- kernel 2: exp + per-chunk sums ----------
__global__ void expsum_kernel() {
    __shared__ float ssum[NC * 2];
    for (int i = threadIdx.x; i < NC * 2; i += blockDim.x) ssum[i] = 0.0f;
    __syncthreads();

    const int gtid = blockIdx.x * blockDim.x + threadIdx.x;
    const int nt   = gridDim.x * blockDim.x;
    for (int e = gtid; e < EE; e += nt) {
        int c = e / STEPC;
        float m0 = fdec(g_maxo[2 * c]);
        float m1 = fdec(g_maxo[2 * c + 1]);
        float p0 = __expf(g_p[2 * e]     - m0);
        float p1 = __expf(g_p[2 * e + 1] - m1);
        g_p[2 * e]     = p0;
        g_p[2 * e + 1] = p1;
        atomicAdd(&ssum[2 * c],     p0);
        atomicAdd(&ssum[2 * c + 1], p1);
    }
    __syncthreads();
    for (int i = threadIdx.x; i < NC * 2; i += blockDim.x)
        if (ssum[i] != 0.0f) atomicAdd(&g_sum[i], ssum[i]);
}

// ---------- kernel 3: fully tensor-core FiLM MLP + att*mod-v + scatter ----------
// 512 threads / 16 warps. Both GEMMs on mma.sync m16n8k8 tf32.
//   Phase 2: C1[64 x 88] = feat[64x24] @ W1^T; warp = (mt = w&3) x (nt1 in {w>>2,+4,+8})
//   Phase 3: C[64 x 352 g'] (g' = 2d+h interleaves gamma/beta);
//            warp = (mg = w&1: m-tiles {2mg,2mg+1}) x (ng = w>>1: 5-6 n-tiles of 44)
struct Smem {
    alignas(16) float w2f[NTT * KT2 * 32 * 4];        // W2 B-frags, 135168 B
    alignas(16) float hfrag[4 * KT2 * 2 * 32 * 4];    // hmid A-frags, 24576 B
    alignas(16) float Sm[TE * DD];                    // 41984 B (v prefetch -> output)
    alignas(16) float featfrag[4 * 3 * 32 * 4];       // feat A-frags, 6144 B
    alignas(8)  float2 w1f[11 * 3 * 32];              // W1 B-frags, 8448 B
    float  b1s[88];                                   // b1 padded
    float2 b2p[DD];                                   // (b2[d], b2[d+164])
    alignas(16) float raw_attr[TE * 16];
    alignas(16) float raw_time[TE];
    alignas(16) int   raw_src[TE];
    alignas(16) int   raw_dst[TE];
    alignas(16) float raw_p[TE * 2];
    int    s_src[TE];
    int    s_dst[TE];
    float  s_att[TE * 2];
    float  s_invsum[NC * 2];
    float  sWt[8], sbt[8];
};

#define NT 512

__device__ __forceinline__ void prefetch_raw(Smem& S, int e0,
                                             const int* ei, const float* edge_attr,
                                             const float* edge_time, int tid) {
    for (int i = tid; i < 256; i += NT)
        cp_async16((unsigned)__cvta_generic_to_shared(&S.raw_attr[0]) + i * 16,
                   edge_attr + (long long)e0 * 16 + i * 4);
    if (tid < 16)
        cp_async16((unsigned)__cvta_generic_to_shared(&S.raw_time[0]) + tid * 16,
                   edge_time + e0 + tid * 4);
    else if (tid < 32) {
        int i = tid - 16;
        cp_async16((unsigned)__cvta_generic_to_shared(&S.raw_src[0]) + i * 16,
                   ei + e0 + i * 4);
    } else if (tid < 48) {
        int i = tid - 32;
        cp_async16((unsigned)__cvta_generic_to_shared(&S.raw_dst[0]) + i * 16,
                   ei + EE + e0 + i * 4);
    } else if (tid < 80) {
        int i = tid - 48;
        cp_async16((unsigned)__cvta_generic_to_shared(&S.raw_p[0]) + i * 16,
                   g_p + 2 * e0 + i * 4);
    }
}

__global__ void __launch_bounds__(NT, 1)
film_attn_kernel(const int* __restrict__ ei, const float* __restrict__ edge_attr,
                 const float* __restrict__ edge_time, const float* __restrict__ Wt,
                 const float* __restrict__ bt, const float* __restrict__ W1,
                 const float* __restrict__ b1, const float* __restrict__ W2,
                 const float* __restrict__ b2, const float* __restrict__ v,
                 float* __restrict__ out) {
    extern __shared__ char sraw[];
    Smem& S = *reinterpret_cast<Smem*>(sraw);
    const int tid = threadIdx.x;

    // ---- prologue staging (once) ----
    // W2 -> B-fragment order, tf32, gamma/beta interleaved columns.
    for (int idx = tid; idx < NTT * KT2 * 32; idx += NT) {
        int lane = idx & 31;
        int rest = idx >> 5;
        int kt2 = rest % KT2;
        int ntg = rest / KT2;
        int gp = 8 * ntg + (lane >> 2);
        int d  = gp >> 1, h = gp & 1;
        int kb = 16 * kt2 + (lane & 3);
        float4 val;
        if (d < DD) {
            const float* wrow = W2 + (long long)(d + DD * h) * DK_;
            val.x = (kb      < DK_) ? __uint_as_float(to_tf32(wrow[kb]))      : 0.0f;
            val.y = (kb + 4  < DK_) ? __uint_as_float(to_tf32(wrow[kb + 4]))  : 0.0f;
            val.z = (kb + 8  < DK_) ? __uint_as_float(to_tf32(wrow[kb + 8]))  : 0.0f;
            val.w = (kb + 12 < DK_) ? __uint_as_float(to_tf32(wrow[kb + 12])) : 0.0f;
        } else {
            val = make_float4(0.f, 0.f, 0.f, 0.f);
        }
        *reinterpret_cast<float4*>(&S.w2f[idx * 4]) = val;
    }
    // hfrag zero-fill (padded k slots 88..95 stay zero forever)
    for (int i = tid; i < 4 * KT2 * 2 * 32; i += NT)
        *reinterpret_cast<float4*>(&S.hfrag[i * 4]) = make_float4(0.f, 0.f, 0.f, 0.f);
    // W1 -> B-fragment order (n = hmid row, k = feat dim; k always < 24)
    for (int idx = tid; idx < 11 * 96; idx += NT) {
        int nt1 = idx / 96, rem = idx % 96;
        int kt = rem / 32, lane = rem % 32;
        int n = 8 * nt1 + (lane >> 2);
        int kk = 8 * kt + (lane & 3);
        float2 val = make_float2(0.f, 0.f);
        if (n < DK_) {
            val.x = __uint_as_float(to_tf32(W1[n * 24 + kk]));
            val.y = __uint_as_float(to_tf32(W1[n * 24 + kk + 4]));
        }
        S.w1f[idx] = val;
    }
    for (int idx = tid; idx < 88; idx += NT) S.b1s[idx] = (idx < DK_) ? b1[idx] : 0.0f;
    for (int idx = tid; idx < DD; idx += NT)
        S.b2p[idx] = make_float2(b2[idx], b2[idx + DD]);
    if (tid < NC * 2) S.s_invsum[tid] = 1.0f / g_sum[tid];
    else if (tid < NC * 2 + 8)  S.sWt[tid - NC * 2] = Wt[tid - NC * 2];
    else if (tid < NC * 2 + 16) S.sbt[tid - NC * 2 - 8] = bt[tid - NC * 2 - 8];

    const int tx   = tid & 31;
    const int warp = tid >> 5;        // 0..15
    // phase-2 mapping
    const int mtw  = warp & 3;        // m-tile for W1 GEMM
    const int ntb1 = warp >> 2;       // base n-tile (of 11)
    // phase-3 mapping
    const int mg   = warp & 1;
    const int ng   = warp >> 1;
    const int ntbase = (ng < 4) ? 6 * ng : 24 + 5 * (ng - 4);
    const int ntcnt  = (ng < 4) ? 6 : 5;
    const unsigned smSm = (unsigned)__cvta_generic_to_shared(&S.Sm[0]);
    const int tile_stride = gridDim.x;

    prefetch_raw(S, blockIdx.x * TE, ei, edge_attr, edge_time, tid);
    asm volatile("cp.async.commit_group;" ::: "memory");

    for (int tile = blockIdx.x; tile < EE / TE; tile += tile_stride) {
        const int e0 = tile * TE;

        asm volatile("cp.async.wait_group 0;" ::: "memory");
        __syncthreads();

        // phase 1: build feat DIRECTLY in A-fragment order (tf32) + edge metadata
        if (tid < 384) {
            int mt = tid / 96, rem = tid % 96;
            int kt = rem / 32, lane = rem % 32;
            int g = lane >> 2, j = lane & 3;
            int el0 = 16 * mt + g, el1 = el0 + 8;
            int k0 = 8 * kt + j, k1 = k0 + 4;
            float v00, v10, v01, v11;
            if (kt < 2) {      // both k0,k1 in edge_attr range
                v00 = S.raw_attr[el0 * 16 + k0]; v10 = S.raw_attr[el1 * 16 + k0];
                v01 = S.raw_attr[el0 * 16 + k1]; v11 = S.raw_attr[el1 * 16 + k1];
            } else {           // both in time_pe range
                float t0 = S.raw_time[el0], t1 = S.raw_time[el1];
                float w0 = S.sWt[k0 - 16], bb0 = S.sbt[k0 - 16];
                float w1v = S.sWt[k1 - 16], bb1 = S.sbt[k1 - 16];
                v00 = fmaf(t0, w0, bb0);  v10 = fmaf(t1, w0, bb0);
                v01 = fmaf(t0, w1v, bb1); v11 = fmaf(t1, w1v, bb1);
            }
            float4 o4;
            o4.x = __uint_as_float(to_tf32(v00));
            o4.y = __uint_as_float(to_tf32(v10));
            o4.z = __uint_as_float(to_tf32(v01));
            o4.w = __uint_as_float(to_tf32(v11));
            *reinterpret_cast<float4*>(&S.featfrag[tid * 4]) = o4;
        }
        if (tid < TE) {
            S.s_src[tid] = S.raw_src[tid];
            S.s_dst[tid] = S.raw_dst[tid];
            int c = (e0 + tid) / STEPC;
            S.s_att[2 * tid]     = S.raw_p[2 * tid]     * S.s_invsum[2 * c];
            S.s_att[2 * tid + 1] = S.raw_p[2 * tid + 1] * S.s_invsum[2 * c + 1];
        }
        __syncthreads();

        // phase 2: hmid = relu(feat @ W1^T + b1) via tf32 MMA -> hfrag (A-frag order)
        {
            uint4 a[3];
#pragma unroll
            for (int kt = 0; kt < 3; kt++) {
                float4 f = *reinterpret_cast<const float4*>(
                    &S.featfrag[((mtw * 3 + kt) * 32 + tx) * 4]);
                a[kt] = make_uint4(__float_as_uint(f.x), __float_as_uint(f.y),
                                   __float_as_uint(f.z), __float_as_uint(f.w));
            }
#pragma unroll
            for (int qq = 0; qq < 3; qq++) {
                int nt1 = ntb1 + 4 * qq;
                if (nt1 < 11) {
                    int r0 = 8 * nt1 + 2 * (tx & 3);
                    float c2[4];
                    c2[0] = S.b1s[r0];     c2[1] = S.b1s[r0 + 1];
                    c2[2] = c2[0];         c2[3] = c2[1];
#pragma unroll
                    for (int kt = 0; kt < 3; kt++) {
                        float2 b = S.w1f[(nt1 * 3 + kt) * 32 + tx];
                        mma_tf32(c2, a[kt].x, a[kt].y, a[kt].z, a[kt].w,
                                 __float_as_uint(b.x), __float_as_uint(b.y));
                    }
#pragma unroll
                    for (int cv = 0; cv < 4; cv++) {
                        int r  = r0 + (cv & 1);
                        int rl = (tx >> 2) + ((cv >> 1) ? 8 : 0);
                        int kt3 = r >> 3, kc = r & 7;
                        int kt2h = kt3 >> 1, ktp = kt3 & 1;
                        int lane2 = ((rl & 7) << 2) | (kc & 3);
                        int slot  = (rl >> 3) | (((kc >> 2) & 1) << 1);
                        unsigned t32 = to_tf32(fmaxf(c2[cv], 0.0f));
                        S.hfrag[((((mtw * KT2 + kt2h) * 2 + ktp) * 32 + lane2) << 2) | slot]
                            = __uint_as_float(t32);
                    }
                }
            }
        }
        __syncthreads();

        // phase 3a: async-prefetch v rows into Sm + next tile's raw inputs
        for (int idx = tid; idx < TE * NQ4; idx += NT) {
            int el = idx / NQ4, c4 = idx % NQ4;
            const float* src = v + (long long)S.s_src[el] * DD + c4 * 4;
            cp_async16(smSm + idx * 16, src);
        }
        {
            int ntile = tile + tile_stride;
            if (ntile < EE / TE)
                prefetch_raw(S, ntile * TE, ei, edge_attr, edge_time, tid);
        }
        asm volatile("cp.async.commit_group;" ::: "memory");

        // phase 3b: tf32 MMA  C[edges x g'] = hmid @ W2'  (+ b2 in C-init)
        {
            float c[2][6][4];
#pragma unroll
            for (int t = 0; t < 6; t++) {
                int d = 4 * (ntbase + t) + (tx & 3);
                int dd = (d < DD) ? d : 0;
                float2 bb = S.b2p[dd];
#pragma unroll
                for (int mtl = 0; mtl < 2; mtl++) {
                    c[mtl][t][0] = bb.x; c[mtl][t][1] = bb.y;
                    c[mtl][t][2] = bb.x; c[mtl][t][3] = bb.y;
                }
            }
#pragma unroll
            for (int kt2 = 0; kt2 < KT2; kt2++) {
                uint4 a[2][2];
#pragma unroll
                for (int mtl = 0; mtl < 2; mtl++) {
                    int mt = 2 * mg + mtl;
                    float4 f0 = *reinterpret_cast<const float4*>(
                        &S.hfrag[(((mt * KT2 + kt2) * 2 + 0) * 32 + tx) * 4]);
                    float4 f1 = *reinterpret_cast<const float4*>(
                        &S.hfrag[(((mt * KT2 + kt2) * 2 + 1) * 32 + tx) * 4]);
                    a[mtl][0] = make_uint4(__float_as_uint(f0.x), __float_as_uint(f0.y),
                                           __float_as_uint(f0.z), __float_as_uint(f0.w));
                    a[mtl][1] = make_uint4(__float_as_uint(f1.x), __float_as_uint(f1.y),
                                           __float_as_uint(f1.z), __float_as_uint(f1.w));
                }
#pragma unroll
                for (int t = 0; t < 6; t++) {
                    if (t < ntcnt) {
                        float4 b = *reinterpret_cast<const float4*>(
                            &S.w2f[(((ntbase + t) * KT2 + kt2) * 32 + tx) * 4]);
                        unsigned b0e = __float_as_uint(b.x), b1e = __float_as_uint(b.y);
                        unsigned b0o = __float_as_uint(b.z), b1o = __float_as_uint(b.w);
#pragma unroll
                        for (int mtl = 0; mtl < 2; mtl++) {
                            mma_tf32(c[mtl][t], a[mtl][0].x, a[mtl][0].y,
                                     a[mtl][0].z, a[mtl][0].w, b0e, b1e);
                            mma_tf32(c[mtl][t], a[mtl][1].x, a[mtl][1].y,
                                     a[mtl][1].z, a[mtl][1].w, b0o, b1o);
                        }
                    }
                }
            }

            asm volatile("cp.async.wait_group 0;" ::: "memory");
            __syncthreads();

            // epilogue: (c0,c1)=(gamma,beta) at el0, (c2,c3) at el0+8; in-register
#pragma unroll
            for (int t = 0; t < 6; t++) {
                if (t < ntcnt) {
                    int d = 4 * (ntbase + t) + (tx & 3);
                    if (d < DD) {
                        int h = (d >= DK_) ? 1 : 0;
#pragma unroll
                        for (int mtl = 0; mtl < 2; mtl++) {
                            int el0 = 32 * mg + 16 * mtl + (tx >> 2);
                            int el1 = el0 + 8;
                            float at0 = S.s_att[2 * el0 + h];
                            float at1 = S.s_att[2 * el1 + h];
                            float g0 = tanh_fast(c[mtl][t][0]);
                            float be0 = tanh_fast(c[mtl][t][1]);
                            float g1 = tanh_fast(c[mtl][t][2]);
                            float be1 = tanh_fast(c[mtl][t][3]);
                            float v0 = S.Sm[el0 * DD + d];
                            float v1 = S.Sm[el1 * DD + d];
                            S.Sm[el0 * DD + d] = at0 * fmaf(v0, 1.0f + g0, be0);
                            S.Sm[el1 * DD + d] = at1 * fmaf(v1, 1.0f + g1, be1);
                        }
                    }
                }
            }
        }
        __syncthreads();

        // phase 4: vectorized scatter-add to out[dst]
        for (int idx = tid; idx < TE * NQ4; idx += NT) {
            int el = idx / NQ4, c4 = idx % NQ4;
            int dN = S.s_dst[el];
            float4 val = *reinterpret_cast<const float4*>(&S.Sm[el * DD + c4 * 4]);
            float* p = out + (long long)dN * DD + c4 * 4;
            asm volatile("red.global.add.v4.f32 [%0], {%1, %2, %3, %4};"
                         :: "l"(p), "f"(val.x), "f"(val.y), "f"(val.z), "f"(val.w)
                         : "memory");
        }
        __syncthreads();
    }
}

extern "C" void kernel_launch(void* const* d_in, const int* in_sizes, int n_in,
                              void* d_out, int out_size) {
    const float* q         = (const float*)d_in[0];
    const float* k         = (const float*)d_in[1];
    const float* v         = (const float*)d_in[2];
    const int*   ei        = (const int*)  d_in[3];
    const float* edge_attr = (const float*)d_in[4];
    const float* edge_time = (const float*)d_in[5];
    const float* Wt        = (const float*)d_in[6];
    const float* bt        = (const float*)d_in[7];
    const float* W1        = (const float*)d_in[8];
    const float* b1        = (const float*)d_in[9];
    const float* W2        = (const float*)d_in[10];
    const float* b2        = (const float*)d_in[11];
    const float* rb        = (const float*)d_in[12];
    float* out = (float*)d_out;

    cudaMemsetAsync(d_out, 0, (size_t)out_size * sizeof(float), 0);
    init_scratch_kernel<<<1, 64>>>();
    score_kernel<<<1184, 256>>>(q, k, ei, rb);
    expsum_kernel<<<1184, 256>>>();

    const int smem_bytes = (int)sizeof(Smem);
    cudaFuncSetAttribute(film_attn_kernel,
                         cudaFuncAttributeMaxDynamicSharedMemorySize, smem_bytes);
    film_attn_kernel<<<152, NT, smem_bytes>>>(ei, edge_attr, edge_time, Wt, bt,
                                              W1, b1, W2, b2, v, out);
}

// round 14
// speedup vs baseline: 4.6610x; 1.0493x over previous
#include <cuda_runtime.h>
#include <cuda_bf16.h>

// Problem constants (fixed by the dataset)
#define NN   100000
#define EE   600000
#define DD   164
#define HH   2
#define DK_  82
#define STEPC 30000
#define NC   20          // EE / STEPC
#define TE   64          // edges per tile in the fused kernel
#define NQ4  41          // DD/4 float4 chunks per row

#define KT2  6           // k padded to 96 -> 12 k8-tiles -> 6 pairs
#define NTT  44          // n8-tiles over gamma/beta-interleaved 352 cols (164*2 pad)

static __device__ float    g_p[EE * 2];      // scores, then probs
static __device__ unsigned g_maxo[NC * 2];   // ordered-encoded per-chunk-per-head max
static __device__ float    g_sum[NC * 2];    // per-chunk-per-head exp sums

#define INV_SQRT_DK 0.11043152607484654f

// ---------- helpers ----------
__device__ __forceinline__ unsigned fenc(float f) {
    unsigned u = __float_as_uint(f);
    return u ^ ((unsigned)((int)u >> 31) | 0x80000000u);
}
__device__ __forceinline__ float fdec(unsigned u) {
    return __uint_as_float(u ^ ((unsigned)((~(int)u) >> 31) | 0x80000000u));
}
__device__ __forceinline__ float tanh_fast(float x) {
    float y;
    asm("tanh.approx.f32 %0, %1;" : "=f"(y) : "f"(x));
    return y;
}
__device__ __forceinline__ unsigned to_tf32(float f) {
    unsigned u;
    asm("cvt.rna.tf32.f32 %0, %1;" : "=r"(u) : "f"(f));
    return u;
}
__device__ __forceinline__ void cp_async16(unsigned smem_dst, const void* gsrc) {
    asm volatile("cp.async.ca.shared.global [%0], [%1], 16;"
                 :: "r"(smem_dst), "l"(gsrc) : "memory");
}
__device__ __forceinline__ void red_add_f32(float* p, float v) {
    asm volatile("red.global.add.f32 [%0], %1;" :: "l"(p), "f"(v) : "memory");
}
__device__ __forceinline__ void mma_tf32(float* c, unsigned a0, unsigned a1,
                                         unsigned a2, unsigned a3,
                                         unsigned b0, unsigned b1) {
    asm volatile("mma.sync.aligned.m16n8k8.row.col.f32.tf32.tf32.f32 "
                 "{%0,%1,%2,%3}, {%4,%5,%6,%7}, {%8,%9}, {%0,%1,%2,%3};"
                 : "+f"(c[0]), "+f"(c[1]), "+f"(c[2]), "+f"(c[3])
                 : "r"(a0), "r"(a1), "r"(a2), "r"(a3), "r"(b0), "r"(b1));
}

// ---------- kernel 0: reset scratch ----------
__global__ void init_scratch_kernel() {
    int i = threadIdx.x;
    if (i < NC * 2) { g_maxo[i] = 0u; g_sum[i] = 0.0f; }
}

// ---------- kernel 1: scores + per-chunk max (vectorized rows) ----------
__global__ void score_kernel(const float* __restrict__ q, const float* __restrict__ k,
                             const int* __restrict__ ei, const float* __restrict__ rb) {
    __shared__ unsigned smax[NC * 2];
    for (int i = threadIdx.x; i < NC * 2; i += blockDim.x) smax[i] = 0u;
    __syncthreads();

    const float rb0 = rb[0], rb1 = rb[1];
    const int lane  = threadIdx.x & 31;
    const int gwarp = (blockIdx.x * blockDim.x + threadIdx.x) >> 5;
    const int nw    = (gridDim.x * blockDim.x) >> 5;

    for (int e = gwarp; e < EE; e += nw) {
        const int sN = ei[e];
        const int dN = ei[EE + e];
        const float* qr = q + (long long)dN * DD;
        const float* kr = k + (long long)sN * DD;
        float s0 = 0.0f, s1 = 0.0f;
        {
            const float4 q4 = *reinterpret_cast<const float4*>(qr + lane * 4);
            const float4 k4 = *reinterpret_cast<const float4*>(kr + lane * 4);
            float px = q4.x * k4.x, py = q4.y * k4.y, pz = q4.z * k4.z, pw = q4.w * k4.w;
            float all = (px + py) + (pz + pw);
            if (lane < 20)      { s0 = all; }
            else if (lane == 20){ s0 = px + py; s1 = pz + pw; }   // d 80,81 | 82,83
            else                { s1 = all; }
        }
        if (lane < 9) {   // chunks 32..40 -> d 128..163, entirely head 1
            const float4 q4 = *reinterpret_cast<const float4*>(qr + 128 + lane * 4);
            const float4 k4 = *reinterpret_cast<const float4*>(kr + 128 + lane * 4);
            s1 += (q4.x * k4.x + q4.y * k4.y) + (q4.z * k4.z + q4.w * k4.w);
        }
#pragma unroll
        for (int o = 16; o; o >>= 1) {
            s0 += __shfl_xor_sync(0xffffffffu, s0, o);
            s1 += __shfl_xor_sync(0xffffffffu, s1, o);
        }
        if (lane == 0) {
            float sc0 = fmaf(s0, INV_SQRT_DK, rb0);
            float sc1 = fmaf(s1, INV_SQRT_DK, rb1);
            g_p[2 * e]     = sc0;
            g_p[2 * e + 1] = sc1;
            int c = e / STEPC;
            atomicMax(&smax[2 * c],     fenc(sc0));
            atomicMax(&smax[2 * c + 1], fenc(sc1));
        }
    }
    __syncthreads();
    for (int i = threadIdx.x; i < NC * 2; i += blockDim.x)
        if (smax[i]) atomicMax(&g_maxo[i], smax[i]);
}

// ---------- kernel 2: exp + per-chunk sums ----------
__global__ void expsum_kernel() {
    __shared__ float ssum[NC * 2];
    for (int i = threadIdx.x; i < NC * 2; i += blockDim.x) ssum[i] = 0.0f;
    __syncthreads();

    const int gtid = blockIdx.x * blockDim.x + threadIdx.x;
    const int nt   = gridDim.x * blockDim.x;
    for (int e = gtid; e < EE; e += nt) {
        int c = e / STEPC;
        float m0 = fdec(g_maxo[2 * c]);
        float m1 = fdec(g_maxo[2 * c + 1]);
        float p0 = __expf(g_p[2 * e]     - m0);
        float p1 = __expf(g_p[2 * e + 1] - m1);
        g_p[2 * e]     = p0;
        g_p[2 * e + 1] = p1;
        atomicAdd(&ssum[2 * c],     p0);
        atomicAdd(&ssum[2 * c + 1], p1);
    }
    __syncthreads();
    for (int i = threadIdx.x; i < NC * 2; i += blockDim.x)
        if (ssum[i] != 0.0f) atomicAdd(&g_sum[i], ssum[i]);
}

// ---------- kernel 3: fully tensor-core FiLM MLP + att*mod-v + direct scatter ----------
// 512 threads / 16 warps. Both GEMMs on mma.sync m16n8k8 tf32.
//   Phase 2: C1[64 x 88] = feat[64x24] @ W1^T; warp = (mt = w&3) x (nt1 in {w>>2,+4,+8})
//   Phase 3: C[64 x 352 g'] (g' = 2d+h interleaves gamma/beta);
//            warp = (mg = w&1: m-tiles {2mg,2mg+1}) x (ng = w>>1: 5-6 n-tiles of 44)
//   Epilogue: final value computed in registers, scattered via scalar red.global.add.
struct Smem {
    alignas(16) float w2f[NTT * KT2 * 32 * 4];        // W2 B-frags, 135168 B
    alignas(16) float hfrag[4 * KT2 * 2 * 32 * 4];    // hmid A-frags, 24576 B
    alignas(16) float Sm[TE * DD];                    // 41984 B (v prefetch)
    alignas(16) float featfrag[4 * 3 * 32 * 4];       // feat A-frags, 6144 B
    alignas(8)  float2 w1f[11 * 3 * 32];              // W1 B-frags, 8448 B
    float  b1s[88];                                   // b1 padded
    float2 b2p[DD];                                   // (b2[d], b2[d+164])
    alignas(16) float raw_attr[TE * 16];
    alignas(16) float raw_time[TE];
    alignas(16) int   raw_src[TE];
    alignas(16) int   raw_dst[TE];
    alignas(16) float raw_p[TE * 2];
    int    s_src[TE];
    int    s_dst[TE];
    float  s_att[TE * 2];
    float  s_invsum[NC * 2];
    float  sWt[8], sbt[8];
};

#define NT 512

__device__ __forceinline__ void prefetch_raw(Smem& S, int e0,
                                             const int* ei, const float* edge_attr,
                                             const float* edge_time, int tid) {
    for (int i = tid; i < 256; i += NT)
        cp_async16((unsigned)__cvta_generic_to_shared(&S.raw_attr[0]) + i * 16,
                   edge_attr + (long long)e0 * 16 + i * 4);
    if (tid < 16)
        cp_async16((unsigned)__cvta_generic_to_shared(&S.raw_time[0]) + tid * 16,
                   edge_time + e0 + tid * 4);
    else if (tid < 32) {
        int i = tid - 16;
        cp_async16((unsigned)__cvta_generic_to_shared(&S.raw_src[0]) + i * 16,
                   ei + e0 + i * 4);
    } else if (tid < 48) {
        int i = tid - 32;
        cp_async16((unsigned)__cvta_generic_to_shared(&S.raw_dst[0]) + i * 16,
                   ei + EE + e0 + i * 4);
    } else if (tid < 80) {
        int i = tid - 48;
        cp_async16((unsigned)__cvta_generic_to_shared(&S.raw_p[0]) + i * 16,
                   g_p + 2 * e0 + i * 4);
    }
}

__global__ void __launch_bounds__(NT, 1)
film_attn_kernel(const int* __restrict__ ei, const float* __restrict__ edge_attr,
                 const float* __restrict__ edge_time, const float* __restrict__ Wt,
                 const float* __restrict__ bt, const float* __restrict__ W1,
                 const float* __restrict__ b1, const float* __restrict__ W2,
                 const float* __restrict__ b2, const float* __restrict__ v,
                 float* __restrict__ out) {
    extern __shared__ char sraw[];
    Smem& S = *reinterpret_cast<Smem*>(sraw);
    const int tid = threadIdx.x;

    // ---- prologue staging (once) ----
    for (int idx = tid; idx < NTT * KT2 * 32; idx += NT) {
        int lane = idx & 31;
        int rest = idx >> 5;
        int kt2 = rest % KT2;
        int ntg = rest / KT2;
        int gp = 8 * ntg + (lane >> 2);
        int d  = gp >> 1, h = gp & 1;
        int kb = 16 * kt2 + (lane & 3);
        float4 val;
        if (d < DD) {
            const float* wrow = W2 + (long long)(d + DD * h) * DK_;
            val.x = (kb      < DK_) ? __uint_as_float(to_tf32(wrow[kb]))      : 0.0f;
            val.y = (kb + 4  < DK_) ? __uint_as_float(to_tf32(wrow[kb + 4]))  : 0.0f;
            val.z = (kb + 8  < DK_) ? __uint_as_float(to_tf32(wrow[kb + 8]))  : 0.0f;
            val.w = (kb + 12 < DK_) ? __uint_as_float(to_tf32(wrow[kb + 12])) : 0.0f;
        } else {
            val = make_float4(0.f, 0.f, 0.f, 0.f);
        }
        *reinterpret_cast<float4*>(&S.w2f[idx * 4]) = val;
    }
    for (int i = tid; i < 4 * KT2 * 2 * 32; i += NT)
        *reinterpret_cast<float4*>(&S.hfrag[i * 4]) = make_float4(0.f, 0.f, 0.f, 0.f);
    for (int idx = tid; idx < 11 * 96; idx += NT) {
        int nt1 = idx / 96, rem = idx % 96;
        int kt = rem / 32, lane = rem % 32;
        int n = 8 * nt1 + (lane >> 2);
        int kk = 8 * kt + (lane & 3);
        float2 val = make_float2(0.f, 0.f);
        if (n < DK_) {
            val.x = __uint_as_float(to_tf32(W1[n * 24 + kk]));
            val.y = __uint_as_float(to_tf32(W1[n * 24 + kk + 4]));
        }
        S.w1f[idx] = val;
    }
    for (int idx = tid; idx < 88; idx += NT) S.b1s[idx] = (idx < DK_) ? b1[idx] : 0.0f;
    for (int idx = tid; idx < DD; idx += NT)
        S.b2p[idx] = make_float2(b2[idx], b2[idx + DD]);
    if (tid < NC * 2) S.s_invsum[tid] = 1.0f / g_sum[tid];
    else if (tid < NC * 2 + 8)  S.sWt[tid - NC * 2] = Wt[tid - NC * 2];
    else if (tid < NC * 2 + 16) S.sbt[tid - NC * 2 - 8] = bt[tid - NC * 2 - 8];

    const int tx   = tid & 31;
    const int warp = tid >> 5;        // 0..15
    const int mtw  = warp & 3;        // phase-2 m-tile
    const int ntb1 = warp >> 2;       // phase-2 base n-tile (of 11)
    const int mg   = warp & 1;        // phase-3 m-group
    const int ng   = warp >> 1;
    const int ntbase = (ng < 4) ? 6 * ng : 24 + 5 * (ng - 4);
    const int ntcnt  = (ng < 4) ? 6 : 5;
    const unsigned smSm = (unsigned)__cvta_generic_to_shared(&S.Sm[0]);
    const int tile_stride = gridDim.x;

    prefetch_raw(S, blockIdx.x * TE, ei, edge_attr, edge_time, tid);
    asm volatile("cp.async.commit_group;" ::: "memory");

    for (int tile = blockIdx.x; tile < EE / TE; tile += tile_stride) {
        const int e0 = tile * TE;

        asm volatile("cp.async.wait_group 0;" ::: "memory");
        __syncthreads();

        // phase 1: build feat DIRECTLY in A-fragment order (tf32) + edge metadata
        if (tid < 384) {
            int mt = tid / 96, rem = tid % 96;
            int kt = rem / 32, lane = rem % 32;
            int g = lane >> 2, j = lane & 3;
            int el0 = 16 * mt + g, el1 = el0 + 8;
            int k0 = 8 * kt + j, k1 = k0 + 4;
            float v00, v10, v01, v11;
            if (kt < 2) {
                v00 = S.raw_attr[el0 * 16 + k0]; v10 = S.raw_attr[el1 * 16 + k0];
                v01 = S.raw_attr[el0 * 16 + k1]; v11 = S.raw_attr[el1 * 16 + k1];
            } else {
                float t0 = S.raw_time[el0], t1 = S.raw_time[el1];
                float w0 = S.sWt[k0 - 16], bb0 = S.sbt[k0 - 16];
                float w1v = S.sWt[k1 - 16], bb1 = S.sbt[k1 - 16];
                v00 = fmaf(t0, w0, bb0);  v10 = fmaf(t1, w0, bb0);
                v01 = fmaf(t0, w1v, bb1); v11 = fmaf(t1, w1v, bb1);
            }
            float4 o4;
            o4.x = __uint_as_float(to_tf32(v00));
            o4.y = __uint_as_float(to_tf32(v10));
            o4.z = __uint_as_float(to_tf32(v01));
            o4.w = __uint_as_float(to_tf32(v11));
            *reinterpret_cast<float4*>(&S.featfrag[tid * 4]) = o4;
        }
        if (tid < TE) {
            S.s_src[tid] = S.raw_src[tid];
            S.s_dst[tid] = S.raw_dst[tid];
            int c = (e0 + tid) / STEPC;
            S.s_att[2 * tid]     = S.raw_p[2 * tid]     * S.s_invsum[2 * c];
            S.s_att[2 * tid + 1] = S.raw_p[2 * tid + 1] * S.s_invsum[2 * c + 1];
        }
        __syncthreads();

        // phase 2: hmid = relu(feat @ W1^T + b1) via tf32 MMA -> hfrag (A-frag order)
        {
            uint4 a[3];
#pragma unroll
            for (int kt = 0; kt < 3; kt++) {
                float4 f = *reinterpret_cast<const float4*>(
                    &S.featfrag[((mtw * 3 + kt) * 32 + tx) * 4]);
                a[kt] = make_uint4(__float_as_uint(f.x), __float_as_uint(f.y),
                                   __float_as_uint(f.z), __float_as_uint(f.w));
            }
#pragma unroll
            for (int qq = 0; qq < 3; qq++) {
                int nt1 = ntb1 + 4 * qq;
                if (nt1 < 11) {
                    int r0 = 8 * nt1 + 2 * (tx & 3);
                    float c2[4];
                    c2[0] = S.b1s[r0];     c2[1] = S.b1s[r0 + 1];
                    c2[2] = c2[0];         c2[3] = c2[1];
#pragma unroll
                    for (int kt = 0; kt < 3; kt++) {
                        float2 b = S.w1f[(nt1 * 3 + kt) * 32 + tx];
                        mma_tf32(c2, a[kt].x, a[kt].y, a[kt].z, a[kt].w,
                                 __float_as_uint(b.x), __float_as_uint(b.y));
                    }
#pragma unroll
                    for (int cv = 0; cv < 4; cv++) {
                        int r  = r0 + (cv & 1);
                        int rl = (tx >> 2) + ((cv >> 1) ? 8 : 0);
                        int kt3 = r >> 3, kc = r & 7;
                        int kt2h = kt3 >> 1, ktp = kt3 & 1;
                        int lane2 = ((rl & 7) << 2) | (kc & 3);
                        int slot  = (rl >> 3) | (((kc >> 2) & 1) << 1);
                        unsigned t32 = to_tf32(fmaxf(c2[cv], 0.0f));
                        S.hfrag[((((mtw * KT2 + kt2h) * 2 + ktp) * 32 + lane2) << 2) | slot]
                            = __uint_as_float(t32);
                    }
                }
            }
        }
        __syncthreads();

        // phase 3a: async-prefetch v rows into Sm + next tile's raw inputs
        for (int idx = tid; idx < TE * NQ4; idx += NT) {
            int el = idx / NQ4, c4 = idx % NQ4;
            const float* src = v + (long long)S.s_src[el] * DD + c4 * 4;
            cp_async16(smSm + idx * 16, src);
        }
        {
            int ntile = tile + tile_stride;
            if (ntile < EE / TE)
                prefetch_raw(S, ntile * TE, ei, edge_attr, edge_time, tid);
        }
        asm volatile("cp.async.commit_group;" ::: "memory");

        // phase 3b: tf32 MMA  C[edges x g'] = hmid @ W2'  (+ b2 in C-init)
        {
            float c[2][6][4];
#pragma unroll
            for (int t = 0; t < 6; t++) {
                int d = 4 * (ntbase + t) + (tx & 3);
                int dd = (d < DD) ? d : 0;
                float2 bb = S.b2p[dd];
#pragma unroll
                for (int mtl = 0; mtl < 2; mtl++) {
                    c[mtl][t][0] = bb.x; c[mtl][t][1] = bb.y;
                    c[mtl][t][2] = bb.x; c[mtl][t][3] = bb.y;
                }
            }
#pragma unroll
            for (int kt2 = 0; kt2 < KT2; kt2++) {
                uint4 a[2][2];
#pragma unroll
                for (int mtl = 0; mtl < 2; mtl++) {
                    int mt = 2 * mg + mtl;
                    float4 f0 = *reinterpret_cast<const float4*>(
                        &S.hfrag[(((mt * KT2 + kt2) * 2 + 0) * 32 + tx) * 4]);
                    float4 f1 = *reinterpret_cast<const float4*>(
                        &S.hfrag[(((mt * KT2 + kt2) * 2 + 1) * 32 + tx) * 4]);
                    a[mtl][0] = make_uint4(__float_as_uint(f0.x), __float_as_uint(f0.y),
                                           __float_as_uint(f0.z), __float_as_uint(f0.w));
                    a[mtl][1] = make_uint4(__float_as_uint(f1.x), __float_as_uint(f1.y),
                                           __float_as_uint(f1.z), __float_as_uint(f1.w));
                }
#pragma unroll
                for (int t = 0; t < 6; t++) {
                    if (t < ntcnt) {
                        float4 b = *reinterpret_cast<const float4*>(
                            &S.w2f[(((ntbase + t) * KT2 + kt2) * 32 + tx) * 4]);
                        unsigned b0e = __float_as_uint(b.x), b1e = __float_as_uint(b.y);
                        unsigned b0o = __float_as_uint(b.z), b1o = __float_as_uint(b.w);
#pragma unroll
                        for (int mtl = 0; mtl < 2; mtl++) {
                            mma_tf32(c[mtl][t], a[mtl][0].x, a[mtl][0].y,
                                     a[mtl][0].z, a[mtl][0].w, b0e, b1e);
                            mma_tf32(c[mtl][t], a[mtl][1].x, a[mtl][1].y,
                                     a[mtl][1].z, a[mtl][1].w, b0o, b1o);
                        }
                    }
                }
            }

            asm volatile("cp.async.wait_group 0;" ::: "memory");
            __syncthreads();

            // epilogue: tanh, v-mod (v from Sm), att -> DIRECT scalar red.global.add
#pragma unroll
            for (int mtl = 0; mtl < 2; mtl++) {
                const int el0 = 32 * mg + 16 * mtl + (tx >> 2);
                const int el1 = el0 + 8;
                const float a00 = S.s_att[2 * el0], a01 = S.s_att[2 * el0 + 1];
                const float a10 = S.s_att[2 * el1], a11 = S.s_att[2 * el1 + 1];
                float* o0 = out + (long long)S.s_dst[el0] * DD;
                float* o1 = out + (long long)S.s_dst[el1] * DD;
                const float* v0r = &S.Sm[el0 * DD];
                const float* v1r = &S.Sm[el1 * DD];
#pragma unroll
                for (int t = 0; t < 6; t++) {
                    if (t < ntcnt) {
                        int d = 4 * (ntbase + t) + (tx & 3);
                        if (d < DD) {
                            bool h1 = (d >= DK_);
                            float at0 = h1 ? a01 : a00;
                            float at1 = h1 ? a11 : a10;
                            float g0 = tanh_fast(c[mtl][t][0]);
                            float be0 = tanh_fast(c[mtl][t][1]);
                            float g1 = tanh_fast(c[mtl][t][2]);
                            float be1 = tanh_fast(c[mtl][t][3]);
                            float r0 = at0 * fmaf(v0r[d], 1.0f + g0, be0);
                            float r1 = at1 * fmaf(v1r[d], 1.0f + g1, be1);
                            red_add_f32(o0 + d, r0);
                            red_add_f32(o1 + d, r1);
                        }
                    }
                }
            }
        }
        // no end-of-loop barrier: loop-top wait_group+syncthreads orders
        // epilogue reads of s_att/s_dst/Sm against next-tile overwrites.
    }
}

extern "C" void kernel_launch(void* const* d_in, const int* in_sizes, int n_in,
                              void* d_out, int out_size) {
    const float* q         = (const float*)d_in[0];
    const float* k         = (const float*)d_in[1];
    const float* v         = (const float*)d_in[2];
    const int*   ei        = (const int*)  d_in[3];
    const float* edge_attr = (const float*)d_in[4];
    const float* edge_time = (const float*)d_in[5];
    const float* Wt        = (const float*)d_in[6];
    const float* bt        = (const float*)d_in[7];
    const float* W1        = (const float*)d_in[8];
    const float* b1        = (const float*)d_in[9];
    const float* W2        = (const float*)d_in[10];
    const float* b2        = (const float*)d_in[11];
    const float* rb        = (const float*)d_in[12];
    float* out = (float*)d_out;

    cudaMemsetAsync(d_out, 0, (size_t)out_size * sizeof(float), 0);
    init_scratch_kernel<<<1, 64>>>();
    score_kernel<<<1184, 256>>>(q, k, ei, rb);
    expsum_kernel<<<1184, 256>>>();

    const int smem_bytes = (int)sizeof(Smem);
    cudaFuncSetAttribute(film_attn_kernel,
                         cudaFuncAttributeMaxDynamicSharedMemorySize, smem_bytes);
    film_attn_kernel<<<152, NT, smem_bytes>>>(ei, edge_attr, edge_time, Wt, bt,
                                              W1, b1, W2, b2, v, out);
}